// round 1
// baseline (speedup 1.0000x reference)
#include <cuda_runtime.h>
#include <cstdint>
#include <cstddef>

#define TPB 256

// ---------- packed f32x2 helpers (Blackwell FFMA2, PTX-only) ----------
__device__ __forceinline__ unsigned long long ffma2(unsigned long long a,
                                                    unsigned long long b,
                                                    unsigned long long c) {
    unsigned long long d;
    asm("fma.rn.f32x2 %0, %1, %2, %3;" : "=l"(d) : "l"(a), "l"(b), "l"(c));
    return d;
}
__device__ __forceinline__ unsigned long long pack2(float lo, float hi) {
    unsigned long long r;
    asm("mov.b64 %0, {%1, %2};" : "=l"(r) : "f"(lo), "f"(hi));
    return r;
}
__device__ __forceinline__ void unpack2(unsigned long long v, float& lo, float& hi) {
    asm("mov.b64 {%0, %1}, %2;" : "=f"(lo), "=f"(hi) : "l"(v));
}

// ---------- activations (MUFU-based, ~1e-5 rel err) ----------
__device__ __forceinline__ float fast_tanh(float x) {
    float xc = fminf(fmaxf(x, -10.0f), 10.0f);   // tanh(10) = 1 - 4e-9
    float e  = __expf(2.0f * xc);
    return __fdividef(e - 1.0f, e + 1.0f);
}
__device__ __forceinline__ float softplus_(float x) {
    return fmaxf(x, 0.0f) + __logf(1.0f + __expf(-fabsf(x)));
}

// ---------- shared memory layout (float offsets) ----------
#define OFF_C     0
#define N_C       (TPB * 129)                 // per-thread C[128], stride 129 (conflict-free)
#define OFF_W2    (OFF_C + N_C)               // dW2 row-major [128][128]
#define OFF_W1Z   (OFF_W2 + 16384)            // [k][12]: dW1 rows 0..9 transposed + t-row + pad
#define OFF_W3T   (OFF_W1Z + 1536)            // dW3 transposed [10][128]
#define OFF_DB2   (OFF_W3T + 1280)            // 128
#define OFF_GW1   (OFF_DB2 + 128)             // 11*32
#define OFF_GB1   (OFF_GW1 + 352)             // 32
#define OFF_GW2   (OFF_GB1 + 32)              // 32*10
#define OFF_GB2   (OFF_GW2 + 320)             // 10 (pad 12)
#define OFF_DB3   (OFF_GB2 + 12)              // 10 (pad 12)
#define OFF_TS    (OFF_DB3 + 12)              // ts, up to 128 entries
#define SMEM_FLOATS (OFF_TS + 128)

__global__ void __launch_bounds__(TPB, 1)
sde_kernel(const float* __restrict__ z0, const float* __restrict__ activity,
           const float* __restrict__ rest, const float* __restrict__ ts,
           const float* __restrict__ noise,
           const float* __restrict__ aW1, const float* __restrict__ ab1,
           const float* __restrict__ aW2, const float* __restrict__ ab2,
           const float* __restrict__ rW1, const float* __restrict__ rb1,
           const float* __restrict__ rW2, const float* __restrict__ rb2,
           const float* __restrict__ dW1, const float* __restrict__ db1,
           const float* __restrict__ dW2, const float* __restrict__ db2,
           const float* __restrict__ dW3, const float* __restrict__ db3,
           const float* __restrict__ gW1, const float* __restrict__ gb1,
           const float* __restrict__ gW2, const float* __restrict__ gb2,
           float* __restrict__ out, int B, int nstep)
{
    extern __shared__ float smem[];
    const int tid  = threadIdx.x;
    const int elem = blockIdx.x * TPB + tid;

    // ---- cooperative weight staging ----
    for (int i = tid; i < 16384; i += TPB) smem[OFF_W2 + i] = dW2[i];
    if (tid < 128) {
        #pragma unroll
        for (int j = 0; j < 10; ++j) smem[OFF_W1Z + tid * 12 + j] = dW1[j * 128 + tid];
        smem[OFF_W1Z + tid * 12 + 10] = dW1[106 * 128 + tid];  // t row
        smem[OFF_W1Z + tid * 12 + 11] = 0.0f;
        smem[OFF_DB2 + tid] = db2[tid];
    }
    for (int i = tid; i < 1280; i += TPB) {
        int o = i & 127, j = i >> 7;
        smem[OFF_W3T + j * 128 + o] = dW3[o * 10 + j];
    }
    for (int i = tid; i < 352; i += TPB) smem[OFF_GW1 + i] = gW1[i];
    if (tid < 32)  smem[OFF_GB1 + tid] = gb1[tid];
    for (int i = tid; i < 320; i += TPB) smem[OFF_GW2 + i] = gW2[i];
    if (tid < 10) { smem[OFF_GB2 + tid] = gb2[tid]; smem[OFF_DB3 + tid] = db3[tid]; }
    for (int i = tid; i <= nstep && i < 128; i += TPB) smem[OFF_TS + i] = ts[i];

    __syncthreads();
    if (elem >= B) return;

    // ---- context encoders (once) ----
    float actv[6], rsv[3];
    #pragma unroll
    for (int j = 0; j < 6; ++j) actv[j] = activity[elem * 6 + j];
    #pragma unroll
    for (int j = 0; j < 3; ++j) rsv[j] = rest[elem * 3 + j];

    float ha[32];
    #pragma unroll
    for (int o = 0; o < 32; ++o) {
        float q = __ldg(&ab1[o]);
        #pragma unroll
        for (int j = 0; j < 6; ++j) q += actv[j] * __ldg(&aW1[j * 32 + o]);
        ha[o] = fmaxf(q, 0.0f);
    }
    float av[64];
    #pragma unroll
    for (int o = 0; o < 64; ++o) {
        float q = __ldg(&ab2[o]);
        #pragma unroll
        for (int j = 0; j < 32; ++j) q += ha[j] * __ldg(&aW2[j * 64 + o]);
        av[o] = q;
    }
    float hr[16];
    #pragma unroll
    for (int o = 0; o < 16; ++o) {
        float q = __ldg(&rb1[o]);
        #pragma unroll
        for (int j = 0; j < 3; ++j) q += rsv[j] * __ldg(&rW1[j * 16 + o]);
        hr[o] = fmaxf(q, 0.0f);
    }
    float rv[32];
    #pragma unroll
    for (int o = 0; o < 32; ++o) {
        float q = __ldg(&rb2[o]);
        #pragma unroll
        for (int j = 0; j < 16; ++j) q += hr[j] * __ldg(&rW2[j * 32 + o]);
        rv[o] = q;
    }

    // ---- fold fixed context into C[128] = a@dW1_a + r@dW1_r + db1 ----
    float* myC = &smem[OFF_C + tid * 129];
    for (int o = 0; o < 128; ++o) {
        float q = __ldg(&db1[o]);
        #pragma unroll
        for (int j = 0; j < 64; ++j) q += av[j] * __ldg(&dW1[(10 + j) * 128 + o]);
        #pragma unroll
        for (int j = 0; j < 32; ++j) q += rv[j] * __ldg(&dW1[(74 + j) * 128 + o]);
        myC[o] = q;
    }

    // ---- z0 and output row 0 ----
    float z[10];
    #pragma unroll
    for (int j = 0; j < 10; ++j) z[j] = z0[elem * 10 + j];
    {
        float2* op0 = (float2*)(out + (size_t)elem * 10);
        #pragma unroll
        for (int j = 0; j < 5; ++j) op0[j] = make_float2(z[2 * j], z[2 * j + 1]);
    }

    // ---- SDE integration ----
    for (int s = 0; s < nstep; ++s) {
        const float t  = smem[OFF_TS + s];
        const float dt = smem[OFF_TS + s + 1] - t;
        const float sq = sqrtf(dt);

        unsigned long long zp[5];
        #pragma unroll
        for (int j = 0; j < 5; ++j) zp[j] = pack2(z[2 * j], z[2 * j + 1]);

        // h2 pre-activation accumulators (128 fp32 as 64 packed pairs)
        unsigned long long acc[64];
        #pragma unroll
        for (int j = 0; j < 64; ++j)
            acc[j] = pack2(smem[OFF_DB2 + 2 * j], smem[OFF_DB2 + 2 * j + 1]);

        // drift layer 1 + 2 fused: produce h1[k] on the fly, rank-1 update into acc
        for (int k = 0; k < 128; ++k) {
            const unsigned long long* w1p =
                (const unsigned long long*)&smem[OFF_W1Z + k * 12];
            unsigned long long p2 = pack2(myC[k], t * smem[OFF_W1Z + k * 12 + 10]);
            #pragma unroll
            for (int j = 0; j < 5; ++j) p2 = ffma2(zp[j], w1p[j], p2);
            float plo, phi; unpack2(p2, plo, phi);
            float h = fast_tanh(plo + phi);
            unsigned long long hh = pack2(h, h);
            const ulonglong2* w2r = (const ulonglong2*)&smem[OFF_W2 + (k << 7)];
            #pragma unroll
            for (int j = 0; j < 32; ++j) {
                ulonglong2 w = w2r[j];
                acc[2 * j]     = ffma2(hh, w.x, acc[2 * j]);
                acc[2 * j + 1] = ffma2(hh, w.y, acc[2 * j + 1]);
            }
        }

        // drift layer 3 (transposed W3, paired over o)
        unsigned long long dzp[10];
        #pragma unroll
        for (int j = 0; j < 10; ++j) dzp[j] = pack2(smem[OFF_DB3 + j], 0.0f);
        #pragma unroll
        for (int o = 0; o < 128; o += 2) {
            float a0, a1; unpack2(acc[o >> 1], a0, a1);
            unsigned long long hp = pack2(fast_tanh(a0), fast_tanh(a1));
            #pragma unroll
            for (int j = 0; j < 10; ++j) {
                unsigned long long w =
                    *(const unsigned long long*)&smem[OFF_W3T + j * 128 + o];
                dzp[j] = ffma2(hp, w, dzp[j]);
            }
        }
        float dz[10];
        #pragma unroll
        for (int j = 0; j < 10; ++j) {
            float lo, hi; unpack2(dzp[j], lo, hi); dz[j] = lo + hi;
        }

        // diffusion MLP 11 -> 32 -> 10
        float gv[10];
        #pragma unroll
        for (int j = 0; j < 10; ++j) gv[j] = smem[OFF_GB2 + j];
        #pragma unroll
        for (int o = 0; o < 32; ++o) {
            float q = smem[OFF_GB1 + o] + t * smem[OFF_GW1 + 10 * 32 + o];
            #pragma unroll
            for (int j = 0; j < 10; ++j) q += z[j] * smem[OFF_GW1 + j * 32 + o];
            q = softplus_(q);
            #pragma unroll
            for (int j = 0; j < 10; ++j) gv[j] += q * smem[OFF_GW2 + o * 10 + j];
        }

        // Euler-Maruyama update + stream out
        const float2* np = (const float2*)(noise + ((size_t)s * B + elem) * 10);
        float2*       op = (float2*)(out + ((size_t)(s + 1) * B + elem) * 10);
        #pragma unroll
        for (int j = 0; j < 5; ++j) {
            float2 e = np[j];
            z[2 * j]     += dz[2 * j]     * dt + gv[2 * j]     * sq * e.x;
            z[2 * j + 1] += dz[2 * j + 1] * dt + gv[2 * j + 1] * sq * e.y;
            op[j] = make_float2(z[2 * j], z[2 * j + 1]);
        }
    }
}

extern "C" void kernel_launch(void* const* d_in, const int* in_sizes, int n_in,
                              void* d_out, int out_size) {
    const float* z0       = (const float*)d_in[0];
    const float* activity = (const float*)d_in[1];
    const float* rest     = (const float*)d_in[2];
    const float* ts       = (const float*)d_in[3];
    const float* noise    = (const float*)d_in[4];
    const float* aW1 = (const float*)d_in[5];
    const float* ab1 = (const float*)d_in[6];
    const float* aW2 = (const float*)d_in[7];
    const float* ab2 = (const float*)d_in[8];
    const float* rW1 = (const float*)d_in[9];
    const float* rb1 = (const float*)d_in[10];
    const float* rW2 = (const float*)d_in[11];
    const float* rb2 = (const float*)d_in[12];
    const float* dW1 = (const float*)d_in[13];
    const float* db1 = (const float*)d_in[14];
    const float* dW2 = (const float*)d_in[15];
    const float* db2 = (const float*)d_in[16];
    const float* dW3 = (const float*)d_in[17];
    const float* db3 = (const float*)d_in[18];
    const float* gW1 = (const float*)d_in[19];
    const float* gb1 = (const float*)d_in[20];
    const float* gW2 = (const float*)d_in[21];
    const float* gb2 = (const float*)d_in[22];

    int B     = in_sizes[0] / 10;
    int nstep = in_sizes[3] - 1;

    size_t smem_bytes = (size_t)SMEM_FLOATS * sizeof(float);
    cudaFuncSetAttribute(sde_kernel, cudaFuncAttributeMaxDynamicSharedMemorySize,
                         (int)smem_bytes);

    int grid = (B + TPB - 1) / TPB;
    sde_kernel<<<grid, TPB, smem_bytes>>>(
        z0, activity, rest, ts, noise,
        aW1, ab1, aW2, ab2, rW1, rb1, rW2, rb2,
        dW1, db1, dW2, db2, dW3, db3,
        gW1, gb1, gW2, gb2,
        (float*)d_out, B, nstep);
}

// round 2
// speedup vs baseline: 1.0009x; 1.0009x over previous
#include <cuda_runtime.h>
#include <cstdint>
#include <cstddef>

#define TPB 256

// ---------- packed f32x2 helpers (Blackwell FFMA2, PTX-only) ----------
__device__ __forceinline__ unsigned long long ffma2(unsigned long long a,
                                                    unsigned long long b,
                                                    unsigned long long c) {
    unsigned long long d;
    asm("fma.rn.f32x2 %0, %1, %2, %3;" : "=l"(d) : "l"(a), "l"(b), "l"(c));
    return d;
}
__device__ __forceinline__ unsigned long long pack2(float lo, float hi) {
    unsigned long long r;
    asm("mov.b64 %0, {%1, %2};" : "=l"(r) : "f"(lo), "f"(hi));
    return r;
}
__device__ __forceinline__ void unpack2(unsigned long long v, float& lo, float& hi) {
    asm("mov.b64 {%0, %1}, %2;" : "=f"(lo), "=f"(hi) : "l"(v));
}

// ---------- activations (MUFU-based, ~1e-5 rel err) ----------
__device__ __forceinline__ float fast_tanh(float x) {
    float xc = fminf(fmaxf(x, -10.0f), 10.0f);   // tanh(10) = 1 - 4e-9
    float e  = __expf(2.0f * xc);
    return __fdividef(e - 1.0f, e + 1.0f);
}
__device__ __forceinline__ float softplus_(float x) {
    return fmaxf(x, 0.0f) + __logf(1.0f + __expf(-fabsf(x)));
}

// ---------- shared memory layout (float offsets) ----------
#define OFF_C     0
#define N_C       (TPB * 129)                 // per-thread C[128], stride 129 (conflict-free)
#define OFF_W2    (OFF_C + N_C)               // dW2 row-major [128][128]
#define OFF_W1Z   (OFF_W2 + 16384)            // [k][12]: dW1 rows 0..9 transposed + t-row + pad
#define OFF_W3T   (OFF_W1Z + 1536)            // dW3 transposed [10][128]
#define OFF_DB2   (OFF_W3T + 1280)            // 128
#define OFF_GW1   (OFF_DB2 + 128)             // 11*32
#define OFF_GB1   (OFF_GW1 + 352)             // 32
#define OFF_GW2   (OFF_GB1 + 32)              // 32*10
#define OFF_GB2   (OFF_GW2 + 320)             // 10 (pad 12)
#define OFF_DB3   (OFF_GB2 + 12)              // 10 (pad 12)
#define OFF_TS    (OFF_DB3 + 12)              // ts, up to 128 entries
#define SMEM_FLOATS (OFF_TS + 128)

__global__ void __launch_bounds__(TPB, 1)
sde_kernel(const float* __restrict__ z0, const float* __restrict__ activity,
           const float* __restrict__ rest, const float* __restrict__ ts,
           const float* __restrict__ noise,
           const float* __restrict__ aW1, const float* __restrict__ ab1,
           const float* __restrict__ aW2, const float* __restrict__ ab2,
           const float* __restrict__ rW1, const float* __restrict__ rb1,
           const float* __restrict__ rW2, const float* __restrict__ rb2,
           const float* __restrict__ dW1, const float* __restrict__ db1,
           const float* __restrict__ dW2, const float* __restrict__ db2,
           const float* __restrict__ dW3, const float* __restrict__ db3,
           const float* __restrict__ gW1, const float* __restrict__ gb1,
           const float* __restrict__ gW2, const float* __restrict__ gb2,
           float* __restrict__ out, int B, int nstep)
{
    extern __shared__ float smem[];
    const int tid  = threadIdx.x;
    const int elem = blockIdx.x * TPB + tid;

    // ---- cooperative weight staging ----
    for (int i = tid; i < 16384; i += TPB) smem[OFF_W2 + i] = dW2[i];
    if (tid < 128) {
        #pragma unroll
        for (int j = 0; j < 10; ++j) smem[OFF_W1Z + tid * 12 + j] = dW1[j * 128 + tid];
        smem[OFF_W1Z + tid * 12 + 10] = dW1[106 * 128 + tid];  // t row
        smem[OFF_W1Z + tid * 12 + 11] = 0.0f;
        smem[OFF_DB2 + tid] = db2[tid];
    }
    for (int i = tid; i < 1280; i += TPB) {
        int o = i & 127, j = i >> 7;
        smem[OFF_W3T + j * 128 + o] = dW3[o * 10 + j];
    }
    for (int i = tid; i < 352; i += TPB) smem[OFF_GW1 + i] = gW1[i];
    if (tid < 32)  smem[OFF_GB1 + tid] = gb1[tid];
    for (int i = tid; i < 320; i += TPB) smem[OFF_GW2 + i] = gW2[i];
    if (tid < 10) { smem[OFF_GB2 + tid] = gb2[tid]; smem[OFF_DB3 + tid] = db3[tid]; }
    for (int i = tid; i <= nstep && i < 128; i += TPB) smem[OFF_TS + i] = ts[i];

    __syncthreads();
    if (elem >= B) return;

    // ---- context encoders (once) ----
    float actv[6], rsv[3];
    #pragma unroll
    for (int j = 0; j < 6; ++j) actv[j] = activity[elem * 6 + j];
    #pragma unroll
    for (int j = 0; j < 3; ++j) rsv[j] = rest[elem * 3 + j];

    float ha[32];
    #pragma unroll
    for (int o = 0; o < 32; ++o) {
        float q = __ldg(&ab1[o]);
        #pragma unroll
        for (int j = 0; j < 6; ++j) q += actv[j] * __ldg(&aW1[j * 32 + o]);
        ha[o] = fmaxf(q, 0.0f);
    }
    float av[64];
    #pragma unroll
    for (int o = 0; o < 64; ++o) {
        float q = __ldg(&ab2[o]);
        #pragma unroll
        for (int j = 0; j < 32; ++j) q += ha[j] * __ldg(&aW2[j * 64 + o]);
        av[o] = q;
    }
    float hr[16];
    #pragma unroll
    for (int o = 0; o < 16; ++o) {
        float q = __ldg(&rb1[o]);
        #pragma unroll
        for (int j = 0; j < 3; ++j) q += rsv[j] * __ldg(&rW1[j * 16 + o]);
        hr[o] = fmaxf(q, 0.0f);
    }
    float rv[32];
    #pragma unroll
    for (int o = 0; o < 32; ++o) {
        float q = __ldg(&rb2[o]);
        #pragma unroll
        for (int j = 0; j < 16; ++j) q += hr[j] * __ldg(&rW2[j * 32 + o]);
        rv[o] = q;
    }

    // ---- fold fixed context into C[128] = a@dW1_a + r@dW1_r + db1 ----
    float* myC = &smem[OFF_C + tid * 129];
    for (int o = 0; o < 128; ++o) {
        float q = __ldg(&db1[o]);
        #pragma unroll
        for (int j = 0; j < 64; ++j) q += av[j] * __ldg(&dW1[(10 + j) * 128 + o]);
        #pragma unroll
        for (int j = 0; j < 32; ++j) q += rv[j] * __ldg(&dW1[(74 + j) * 128 + o]);
        myC[o] = q;
    }

    // ---- z0 and output row 0 ----
    float z[10];
    #pragma unroll
    for (int j = 0; j < 10; ++j) z[j] = z0[elem * 10 + j];
    {
        float2* op0 = (float2*)(out + (size_t)elem * 10);
        #pragma unroll
        for (int j = 0; j < 5; ++j) op0[j] = make_float2(z[2 * j], z[2 * j + 1]);
    }

    // ---- SDE integration ----
    for (int s = 0; s < nstep; ++s) {
        const float t  = smem[OFF_TS + s];
        const float dt = smem[OFF_TS + s + 1] - t;
        const float sq = sqrtf(dt);

        unsigned long long zp[5];
        #pragma unroll
        for (int j = 0; j < 5; ++j) zp[j] = pack2(z[2 * j], z[2 * j + 1]);

        // h2 pre-activation accumulators (128 fp32 as 64 packed pairs)
        unsigned long long acc[64];
        #pragma unroll
        for (int j = 0; j < 64; ++j)
            acc[j] = pack2(smem[OFF_DB2 + 2 * j], smem[OFF_DB2 + 2 * j + 1]);

        // drift layer 1 + 2 fused: produce h1[k] on the fly, rank-1 update into acc
        for (int k = 0; k < 128; ++k) {
            const unsigned long long* w1p =
                (const unsigned long long*)&smem[OFF_W1Z + k * 12];
            unsigned long long p2 = pack2(myC[k], t * smem[OFF_W1Z + k * 12 + 10]);
            #pragma unroll
            for (int j = 0; j < 5; ++j) p2 = ffma2(zp[j], w1p[j], p2);
            float plo, phi; unpack2(p2, plo, phi);
            float h = fast_tanh(plo + phi);
            unsigned long long hh = pack2(h, h);
            const ulonglong2* w2r = (const ulonglong2*)&smem[OFF_W2 + (k << 7)];
            #pragma unroll
            for (int j = 0; j < 32; ++j) {
                ulonglong2 w = w2r[j];
                acc[2 * j]     = ffma2(hh, w.x, acc[2 * j]);
                acc[2 * j + 1] = ffma2(hh, w.y, acc[2 * j + 1]);
            }
        }

        // drift layer 3 (transposed W3, paired over o)
        unsigned long long dzp[10];
        #pragma unroll
        for (int j = 0; j < 10; ++j) dzp[j] = pack2(smem[OFF_DB3 + j], 0.0f);
        #pragma unroll
        for (int o = 0; o < 128; o += 2) {
            float a0, a1; unpack2(acc[o >> 1], a0, a1);
            unsigned long long hp = pack2(fast_tanh(a0), fast_tanh(a1));
            #pragma unroll
            for (int j = 0; j < 10; ++j) {
                unsigned long long w =
                    *(const unsigned long long*)&smem[OFF_W3T + j * 128 + o];
                dzp[j] = ffma2(hp, w, dzp[j]);
            }
        }
        float dz[10];
        #pragma unroll
        for (int j = 0; j < 10; ++j) {
            float lo, hi; unpack2(dzp[j], lo, hi); dz[j] = lo + hi;
        }

        // diffusion MLP 11 -> 32 -> 10
        float gv[10];
        #pragma unroll
        for (int j = 0; j < 10; ++j) gv[j] = smem[OFF_GB2 + j];
        #pragma unroll
        for (int o = 0; o < 32; ++o) {
            float q = smem[OFF_GB1 + o] + t * smem[OFF_GW1 + 10 * 32 + o];
            #pragma unroll
            for (int j = 0; j < 10; ++j) q += z[j] * smem[OFF_GW1 + j * 32 + o];
            q = softplus_(q);
            #pragma unroll
            for (int j = 0; j < 10; ++j) gv[j] += q * smem[OFF_GW2 + o * 10 + j];
        }

        // Euler-Maruyama update + stream out
        const float2* np = (const float2*)(noise + ((size_t)s * B + elem) * 10);
        float2*       op = (float2*)(out + ((size_t)(s + 1) * B + elem) * 10);
        #pragma unroll
        for (int j = 0; j < 5; ++j) {
            float2 e = np[j];
            z[2 * j]     += dz[2 * j]     * dt + gv[2 * j]     * sq * e.x;
            z[2 * j + 1] += dz[2 * j + 1] * dt + gv[2 * j + 1] * sq * e.y;
            op[j] = make_float2(z[2 * j], z[2 * j + 1]);
        }
    }
}

extern "C" void kernel_launch(void* const* d_in, const int* in_sizes, int n_in,
                              void* d_out, int out_size) {
    const float* z0       = (const float*)d_in[0];
    const float* activity = (const float*)d_in[1];
    const float* rest     = (const float*)d_in[2];
    const float* ts       = (const float*)d_in[3];
    const float* noise    = (const float*)d_in[4];
    const float* aW1 = (const float*)d_in[5];
    const float* ab1 = (const float*)d_in[6];
    const float* aW2 = (const float*)d_in[7];
    const float* ab2 = (const float*)d_in[8];
    const float* rW1 = (const float*)d_in[9];
    const float* rb1 = (const float*)d_in[10];
    const float* rW2 = (const float*)d_in[11];
    const float* rb2 = (const float*)d_in[12];
    const float* dW1 = (const float*)d_in[13];
    const float* db1 = (const float*)d_in[14];
    const float* dW2 = (const float*)d_in[15];
    const float* db2 = (const float*)d_in[16];
    const float* dW3 = (const float*)d_in[17];
    const float* db3 = (const float*)d_in[18];
    const float* gW1 = (const float*)d_in[19];
    const float* gb1 = (const float*)d_in[20];
    const float* gW2 = (const float*)d_in[21];
    const float* gb2 = (const float*)d_in[22];

    int B     = in_sizes[0] / 10;
    int nstep = in_sizes[3] - 1;

    size_t smem_bytes = (size_t)SMEM_FLOATS * sizeof(float);
    cudaFuncSetAttribute(sde_kernel, cudaFuncAttributeMaxDynamicSharedMemorySize,
                         (int)smem_bytes);

    int grid = (B + TPB - 1) / TPB;
    sde_kernel<<<grid, TPB, smem_bytes>>>(
        z0, activity, rest, ts, noise,
        aW1, ab1, aW2, ab2, rW1, rb1, rW2, rb2,
        dW1, db1, dW2, db2, dW3, db3,
        gW1, gb1, gW2, gb2,
        (float*)d_out, B, nstep);
}

// round 3
// speedup vs baseline: 1.0025x; 1.0016x over previous
#include <cuda_runtime.h>
#include <cstdint>
#include <cstddef>

#define TPB 256

// ---------- packed f32x2 helpers (Blackwell FFMA2, PTX-only) ----------
__device__ __forceinline__ unsigned long long ffma2(unsigned long long a,
                                                    unsigned long long b,
                                                    unsigned long long c) {
    unsigned long long d;
    asm("fma.rn.f32x2 %0, %1, %2, %3;" : "=l"(d) : "l"(a), "l"(b), "l"(c));
    return d;
}
__device__ __forceinline__ unsigned long long pack2(float lo, float hi) {
    unsigned long long r;
    asm("mov.b64 %0, {%1, %2};" : "=l"(r) : "f"(lo), "f"(hi));
    return r;
}
__device__ __forceinline__ void unpack2(unsigned long long v, float& lo, float& hi) {
    asm("mov.b64 {%0, %1}, %2;" : "=f"(lo), "=f"(hi) : "l"(v));
}

// ---------- activations (MUFU-based, ~1e-5 rel err) ----------
__device__ __forceinline__ float fast_tanh(float x) {
    float xc = fminf(fmaxf(x, -10.0f), 10.0f);   // tanh(10) = 1 - 4e-9
    float e  = __expf(2.0f * xc);
    return __fdividef(e - 1.0f, e + 1.0f);
}
__device__ __forceinline__ float softplus_(float x) {
    return fmaxf(x, 0.0f) + __logf(1.0f + __expf(-fabsf(x)));
}

// ---------- shared memory layout (float offsets) ----------
#define OFF_C     0
#define N_C       (TPB * 129)                 // per-thread C[128], stride 129 (conflict-free)
#define OFF_W2    (OFF_C + N_C)               // dW2 row-major [128][128]
#define OFF_W1Z   (OFF_W2 + 16384)            // [k][12]: dW1 rows 0..9 transposed + t-row + pad
#define OFF_W3T   (OFF_W1Z + 1536)            // dW3 transposed [10][128]
#define OFF_DB2   (OFF_W3T + 1280)            // 128
#define OFF_GW1   (OFF_DB2 + 128)             // 11*32
#define OFF_GB1   (OFF_GW1 + 352)             // 32
#define OFF_GW2   (OFF_GB1 + 32)              // 32*10
#define OFF_GB2   (OFF_GW2 + 320)             // 10 (pad 12)
#define OFF_DB3   (OFF_GB2 + 12)              // 10 (pad 12)
#define OFF_TS    (OFF_DB3 + 12)              // ts, up to 128 entries
#define SMEM_FLOATS (OFF_TS + 128)

__global__ void __launch_bounds__(TPB, 1)
sde_kernel(const float* __restrict__ z0, const float* __restrict__ activity,
           const float* __restrict__ rest, const float* __restrict__ ts,
           const float* __restrict__ noise,
           const float* __restrict__ aW1, const float* __restrict__ ab1,
           const float* __restrict__ aW2, const float* __restrict__ ab2,
           const float* __restrict__ rW1, const float* __restrict__ rb1,
           const float* __restrict__ rW2, const float* __restrict__ rb2,
           const float* __restrict__ dW1, const float* __restrict__ db1,
           const float* __restrict__ dW2, const float* __restrict__ db2,
           const float* __restrict__ dW3, const float* __restrict__ db3,
           const float* __restrict__ gW1, const float* __restrict__ gb1,
           const float* __restrict__ gW2, const float* __restrict__ gb2,
           float* __restrict__ out, int B, int nstep)
{
    extern __shared__ float smem[];
    const int tid  = threadIdx.x;
    const int elem = blockIdx.x * TPB + tid;

    // ---- cooperative weight staging ----
    for (int i = tid; i < 16384; i += TPB) smem[OFF_W2 + i] = dW2[i];
    if (tid < 128) {
        #pragma unroll
        for (int j = 0; j < 10; ++j) smem[OFF_W1Z + tid * 12 + j] = dW1[j * 128 + tid];
        smem[OFF_W1Z + tid * 12 + 10] = dW1[106 * 128 + tid];  // t row
        smem[OFF_W1Z + tid * 12 + 11] = 0.0f;
        smem[OFF_DB2 + tid] = db2[tid];
    }
    for (int i = tid; i < 1280; i += TPB) {
        int o = i & 127, j = i >> 7;
        smem[OFF_W3T + j * 128 + o] = dW3[o * 10 + j];
    }
    for (int i = tid; i < 352; i += TPB) smem[OFF_GW1 + i] = gW1[i];
    if (tid < 32)  smem[OFF_GB1 + tid] = gb1[tid];
    for (int i = tid; i < 320; i += TPB) smem[OFF_GW2 + i] = gW2[i];
    if (tid < 10) { smem[OFF_GB2 + tid] = gb2[tid]; smem[OFF_DB3 + tid] = db3[tid]; }
    for (int i = tid; i <= nstep && i < 128; i += TPB) smem[OFF_TS + i] = ts[i];

    __syncthreads();
    if (elem >= B) return;

    // ---- context encoders (once) ----
    float actv[6], rsv[3];
    #pragma unroll
    for (int j = 0; j < 6; ++j) actv[j] = activity[elem * 6 + j];
    #pragma unroll
    for (int j = 0; j < 3; ++j) rsv[j] = rest[elem * 3 + j];

    float ha[32];
    #pragma unroll
    for (int o = 0; o < 32; ++o) {
        float q = __ldg(&ab1[o]);
        #pragma unroll
        for (int j = 0; j < 6; ++j) q += actv[j] * __ldg(&aW1[j * 32 + o]);
        ha[o] = fmaxf(q, 0.0f);
    }
    float av[64];
    #pragma unroll
    for (int o = 0; o < 64; ++o) {
        float q = __ldg(&ab2[o]);
        #pragma unroll
        for (int j = 0; j < 32; ++j) q += ha[j] * __ldg(&aW2[j * 64 + o]);
        av[o] = q;
    }
    float hr[16];
    #pragma unroll
    for (int o = 0; o < 16; ++o) {
        float q = __ldg(&rb1[o]);
        #pragma unroll
        for (int j = 0; j < 3; ++j) q += rsv[j] * __ldg(&rW1[j * 16 + o]);
        hr[o] = fmaxf(q, 0.0f);
    }
    float rv[32];
    #pragma unroll
    for (int o = 0; o < 32; ++o) {
        float q = __ldg(&rb2[o]);
        #pragma unroll
        for (int j = 0; j < 16; ++j) q += hr[j] * __ldg(&rW2[j * 32 + o]);
        rv[o] = q;
    }

    // ---- fold fixed context into C[128] = a@dW1_a + r@dW1_r + db1 ----
    float* myC = &smem[OFF_C + tid * 129];
    for (int o = 0; o < 128; ++o) {
        float q = __ldg(&db1[o]);
        #pragma unroll
        for (int j = 0; j < 64; ++j) q += av[j] * __ldg(&dW1[(10 + j) * 128 + o]);
        #pragma unroll
        for (int j = 0; j < 32; ++j) q += rv[j] * __ldg(&dW1[(74 + j) * 128 + o]);
        myC[o] = q;
    }

    // ---- z0 and output row 0 ----
    float z[10];
    #pragma unroll
    for (int j = 0; j < 10; ++j) z[j] = z0[elem * 10 + j];
    {
        float2* op0 = (float2*)(out + (size_t)elem * 10);
        #pragma unroll
        for (int j = 0; j < 5; ++j) op0[j] = make_float2(z[2 * j], z[2 * j + 1]);
    }

    // ---- SDE integration ----
    for (int s = 0; s < nstep; ++s) {
        const float t  = smem[OFF_TS + s];
        const float dt = smem[OFF_TS + s + 1] - t;
        const float sq = sqrtf(dt);

        unsigned long long zp[5];
        #pragma unroll
        for (int j = 0; j < 5; ++j) zp[j] = pack2(z[2 * j], z[2 * j + 1]);

        // h2 pre-activation accumulators (128 fp32 as 64 packed pairs)
        unsigned long long acc[64];
        #pragma unroll
        for (int j = 0; j < 64; ++j)
            acc[j] = pack2(smem[OFF_DB2 + 2 * j], smem[OFF_DB2 + 2 * j + 1]);

        // drift layer 1 + 2 fused: produce h1[k] on the fly, rank-1 update into acc
        for (int k = 0; k < 128; ++k) {
            const unsigned long long* w1p =
                (const unsigned long long*)&smem[OFF_W1Z + k * 12];
            unsigned long long p2 = pack2(myC[k], t * smem[OFF_W1Z + k * 12 + 10]);
            #pragma unroll
            for (int j = 0; j < 5; ++j) p2 = ffma2(zp[j], w1p[j], p2);
            float plo, phi; unpack2(p2, plo, phi);
            float h = fast_tanh(plo + phi);
            unsigned long long hh = pack2(h, h);
            const ulonglong2* w2r = (const ulonglong2*)&smem[OFF_W2 + (k << 7)];
            #pragma unroll
            for (int j = 0; j < 32; ++j) {
                ulonglong2 w = w2r[j];
                acc[2 * j]     = ffma2(hh, w.x, acc[2 * j]);
                acc[2 * j + 1] = ffma2(hh, w.y, acc[2 * j + 1]);
            }
        }

        // drift layer 3 (transposed W3, paired over o)
        unsigned long long dzp[10];
        #pragma unroll
        for (int j = 0; j < 10; ++j) dzp[j] = pack2(smem[OFF_DB3 + j], 0.0f);
        #pragma unroll
        for (int o = 0; o < 128; o += 2) {
            float a0, a1; unpack2(acc[o >> 1], a0, a1);
            unsigned long long hp = pack2(fast_tanh(a0), fast_tanh(a1));
            #pragma unroll
            for (int j = 0; j < 10; ++j) {
                unsigned long long w =
                    *(const unsigned long long*)&smem[OFF_W3T + j * 128 + o];
                dzp[j] = ffma2(hp, w, dzp[j]);
            }
        }
        float dz[10];
        #pragma unroll
        for (int j = 0; j < 10; ++j) {
            float lo, hi; unpack2(dzp[j], lo, hi); dz[j] = lo + hi;
        }

        // diffusion MLP 11 -> 32 -> 10
        float gv[10];
        #pragma unroll
        for (int j = 0; j < 10; ++j) gv[j] = smem[OFF_GB2 + j];
        #pragma unroll
        for (int o = 0; o < 32; ++o) {
            float q = smem[OFF_GB1 + o] + t * smem[OFF_GW1 + 10 * 32 + o];
            #pragma unroll
            for (int j = 0; j < 10; ++j) q += z[j] * smem[OFF_GW1 + j * 32 + o];
            q = softplus_(q);
            #pragma unroll
            for (int j = 0; j < 10; ++j) gv[j] += q * smem[OFF_GW2 + o * 10 + j];
        }

        // Euler-Maruyama update + stream out
        const float2* np = (const float2*)(noise + ((size_t)s * B + elem) * 10);
        float2*       op = (float2*)(out + ((size_t)(s + 1) * B + elem) * 10);
        #pragma unroll
        for (int j = 0; j < 5; ++j) {
            float2 e = np[j];
            z[2 * j]     += dz[2 * j]     * dt + gv[2 * j]     * sq * e.x;
            z[2 * j + 1] += dz[2 * j + 1] * dt + gv[2 * j + 1] * sq * e.y;
            op[j] = make_float2(z[2 * j], z[2 * j + 1]);
        }
    }
}

extern "C" void kernel_launch(void* const* d_in, const int* in_sizes, int n_in,
                              void* d_out, int out_size) {
    const float* z0       = (const float*)d_in[0];
    const float* activity = (const float*)d_in[1];
    const float* rest     = (const float*)d_in[2];
    const float* ts       = (const float*)d_in[3];
    const float* noise    = (const float*)d_in[4];
    const float* aW1 = (const float*)d_in[5];
    const float* ab1 = (const float*)d_in[6];
    const float* aW2 = (const float*)d_in[7];
    const float* ab2 = (const float*)d_in[8];
    const float* rW1 = (const float*)d_in[9];
    const float* rb1 = (const float*)d_in[10];
    const float* rW2 = (const float*)d_in[11];
    const float* rb2 = (const float*)d_in[12];
    const float* dW1 = (const float*)d_in[13];
    const float* db1 = (const float*)d_in[14];
    const float* dW2 = (const float*)d_in[15];
    const float* db2 = (const float*)d_in[16];
    const float* dW3 = (const float*)d_in[17];
    const float* db3 = (const float*)d_in[18];
    const float* gW1 = (const float*)d_in[19];
    const float* gb1 = (const float*)d_in[20];
    const float* gW2 = (const float*)d_in[21];
    const float* gb2 = (const float*)d_in[22];

    int B     = in_sizes[0] / 10;
    int nstep = in_sizes[3] - 1;

    size_t smem_bytes = (size_t)SMEM_FLOATS * sizeof(float);
    cudaFuncSetAttribute(sde_kernel, cudaFuncAttributeMaxDynamicSharedMemorySize,
                         (int)smem_bytes);

    int grid = (B + TPB - 1) / TPB;
    sde_kernel<<<grid, TPB, smem_bytes>>>(
        z0, activity, rest, ts, noise,
        aW1, ab1, aW2, ab2, rW1, rb1, rW2, rb2,
        dW1, db1, dW2, db2, dW3, db3,
        gW1, gb1, gW2, gb2,
        (float*)d_out, B, nstep);
}

// round 6
// speedup vs baseline: 3.1772x; 3.1693x over previous
#include <cuda_runtime.h>
#include <cuda_bf16.h>
#include <cstdint>
#include <cstddef>

#define TPB 256
#define NWARP 8

typedef unsigned long long ull;

// C context scratch: layout Cq[k/4][elem] as float4 (coalesced per-warp reads).
// Sized for the fixed dataset B = 32768.
__device__ float4 g_C[32 * 32768];

// ---------------- packed f32x2 (Blackwell FFMA2) ----------------
__device__ __forceinline__ ull ffma2(ull a, ull b, ull c) {
    ull d; asm("fma.rn.f32x2 %0, %1, %2, %3;" : "=l"(d) : "l"(a), "l"(b), "l"(c)); return d;
}
__device__ __forceinline__ ull pack2(float lo, float hi) {
    ull r; asm("mov.b64 %0, {%1, %2};" : "=l"(r) : "f"(lo), "f"(hi)); return r;
}
__device__ __forceinline__ void unpack2(ull v, float& lo, float& hi) {
    asm("mov.b64 {%0, %1}, %2;" : "=f"(lo), "=f"(hi) : "l"(v));
}
__device__ __forceinline__ uint32_t bf16x2_of(float lo, float hi) {
    uint32_t r; asm("cvt.rn.bf16x2.f32 %0, %1, %2;" : "=r"(r) : "f"(hi), "f"(lo)); return r;
}
// ---------------- activations ----------------
__device__ __forceinline__ float tanh_hw(float x) {     // h1 (feeds bf16 anyway)
    float y; asm("tanh.approx.f32 %0, %1;" : "=f"(y) : "f"(x)); return y;
}
__device__ __forceinline__ float tanh_acc(float x) {    // h2, accurate ~1e-7
    float xc = fminf(fmaxf(x, -10.0f), 10.0f);
    float e  = __expf(2.0f * xc);
    return __fdividef(e - 1.0f, e + 1.0f);
}
__device__ __forceinline__ float softplus_(float x) {
    return fmaxf(x, 0.0f) + __logf(1.0f + __expf(-fabsf(x)));
}
// ---------------- tensor-core ops (baseline PTX, no 'a' needed) ----------------
__device__ __forceinline__ void mma16816(float* c, const uint32_t* a, uint32_t b0, uint32_t b1) {
    asm volatile("mma.sync.aligned.m16n8k16.row.col.f32.bf16.bf16.f32 "
        "{%0,%1,%2,%3}, {%4,%5,%6,%7}, {%8,%9}, {%0,%1,%2,%3};"
        : "+f"(c[0]), "+f"(c[1]), "+f"(c[2]), "+f"(c[3])
        : "r"(a[0]), "r"(a[1]), "r"(a[2]), "r"(a[3]), "r"(b0), "r"(b1));
}
__device__ __forceinline__ void ldm_x4(uint32_t* r, uint32_t addr) {
    asm volatile("ldmatrix.sync.aligned.m8n8.x4.shared.b16 {%0,%1,%2,%3}, [%4];"
        : "=r"(r[0]), "=r"(r[1]), "=r"(r[2]), "=r"(r[3]) : "r"(addr));
}
__device__ __forceinline__ uint32_t smem_u32(const void* p) {
    uint32_t a;
    asm("{ .reg .u64 t; cvta.to.shared.u64 t, %1; cvt.u32.u64 %0, t; }" : "=r"(a) : "l"(p));
    return a;
}

// ---------------- SMEM byte layout ----------------
// A tiles: per warp 32 rows x 128 bf16, row stride 272B (256 + 16 pad: conflict-free ldmatrix)
#define A_BYTE     0
#define A_WSTRIDE  (32 * 272)                 // 8704 per warp
#define BHI_BYTE   69632                      // W2^T hi: 128 rows(n) x 128 bf16, stride 272
#define BLO_BYTE   104448                     // W2^T lo
#define W1_BYTE    139264                     // [128][16] floats: w0..w9, wt, pad
#define W3_BYTE    147456                     // [128][12] floats
#define DB2_BYTE   153600                     // [128]
#define GW1_BYTE   154112                     // [32][12]: gj0..gj9, gt, pad
#define GW2_BYTE   155648                     // [32][12]
#define GB1_BYTE   157184                     // [32]
#define TS_BYTE    157312                     // [128]
#define GB2_BYTE   157824                     // [12]
#define DB3_BYTE   157872                     // [12]
#define ROUTE_BYTE 157920                     // [8 warps][32 rows][12 floats]
#define SMEM_BYTES (157920 + 8 * 32 * 12 * 4) // 170208

__global__ void __launch_bounds__(TPB, 1)
sde_hmma(const float* __restrict__ z0, const float* __restrict__ activity,
         const float* __restrict__ rest, const float* __restrict__ ts,
         const float* __restrict__ noise,
         const float* __restrict__ aW1, const float* __restrict__ ab1,
         const float* __restrict__ aW2, const float* __restrict__ ab2,
         const float* __restrict__ rW1, const float* __restrict__ rb1,
         const float* __restrict__ rW2, const float* __restrict__ rb2,
         const float* __restrict__ dW1, const float* __restrict__ db1,
         const float* __restrict__ dW2, const float* __restrict__ db2,
         const float* __restrict__ dW3, const float* __restrict__ db3,
         const float* __restrict__ gW1, const float* __restrict__ gb1,
         const float* __restrict__ gW2, const float* __restrict__ gb2,
         float* __restrict__ out, int Bn, int nstep)
{
    extern __shared__ char smc[];
    const uint32_t sbase = smem_u32(smc);
    const int tid  = threadIdx.x;
    const int wid  = tid >> 5;
    const int lane = tid & 31;
    const int elem = blockIdx.x * TPB + tid;
    const int qc   = (lane & 3) * 2;          // fragment col pair base

    // ================= one-time staging =================
    // W2^T hi/lo bf16: BT[n][k] at n*272 + 2k
    for (int i = tid; i < 16384; i += TPB) {
        int k = i >> 7, n = i & 127;
        float w = dW2[i];
        __nv_bfloat16 hi = __float2bfloat16(w);
        __nv_bfloat16 lo = __float2bfloat16(w - __bfloat162float(hi));
        uint32_t off = (uint32_t)n * 272u + (uint32_t)k * 2u;
        *(__nv_bfloat16*)(smc + BHI_BYTE + off) = hi;
        *(__nv_bfloat16*)(smc + BLO_BYTE + off) = lo;
    }
    if (tid < 128) {
        float* w1r = (float*)(smc + W1_BYTE + tid * 64);
        #pragma unroll
        for (int j = 0; j < 10; ++j) w1r[j] = dW1[j * 128 + tid];
        w1r[10] = dW1[106 * 128 + tid];       // t row
        w1r[11] = 0.0f; w1r[12] = 0.0f; w1r[13] = 0.0f; w1r[14] = 0.0f; w1r[15] = 0.0f;
        ((float*)(smc + DB2_BYTE))[tid] = db2[tid];
        float* w3r = (float*)(smc + W3_BYTE + tid * 48);
        #pragma unroll
        for (int j = 0; j < 10; ++j) w3r[j] = dW3[tid * 10 + j];
        w3r[10] = 0.0f; w3r[11] = 0.0f;
    }
    if (tid < 32) {
        float* g1r = (float*)(smc + GW1_BYTE + tid * 48);
        #pragma unroll
        for (int j = 0; j < 10; ++j) g1r[j] = gW1[j * 32 + tid];
        g1r[10] = gW1[10 * 32 + tid];
        g1r[11] = 0.0f;
        float* g2r = (float*)(smc + GW2_BYTE + tid * 48);
        #pragma unroll
        for (int j = 0; j < 10; ++j) g2r[j] = gW2[tid * 10 + j];
        g2r[10] = 0.0f; g2r[11] = 0.0f;
        ((float*)(smc + GB1_BYTE))[tid] = gb1[tid];
    }
    if (tid < 12) {
        ((float*)(smc + GB2_BYTE))[tid] = (tid < 10) ? gb2[tid] : 0.0f;
        ((float*)(smc + DB3_BYTE))[tid] = (tid < 10) ? db3[tid] : 0.0f;
    }
    for (int i = tid; i <= nstep && i < 128; i += TPB)
        ((float*)(smc + TS_BYTE))[i] = ts[i];

    // ---- context encoders -> C[128] -> g_C transposed float4 ----
    {
        float actv[6], rsv[3];
        #pragma unroll
        for (int j = 0; j < 6; ++j) actv[j] = activity[elem * 6 + j];
        #pragma unroll
        for (int j = 0; j < 3; ++j) rsv[j] = rest[elem * 3 + j];
        float ha[32];
        #pragma unroll
        for (int o = 0; o < 32; ++o) {
            float q = __ldg(&ab1[o]);
            #pragma unroll
            for (int j = 0; j < 6; ++j) q += actv[j] * __ldg(&aW1[j * 32 + o]);
            ha[o] = fmaxf(q, 0.0f);
        }
        float av[64];
        #pragma unroll
        for (int o = 0; o < 64; ++o) {
            float q = __ldg(&ab2[o]);
            #pragma unroll
            for (int j = 0; j < 32; ++j) q += ha[j] * __ldg(&aW2[j * 64 + o]);
            av[o] = q;
        }
        float hr[16];
        #pragma unroll
        for (int o = 0; o < 16; ++o) {
            float q = __ldg(&rb1[o]);
            #pragma unroll
            for (int j = 0; j < 3; ++j) q += rsv[j] * __ldg(&rW1[j * 16 + o]);
            hr[o] = fmaxf(q, 0.0f);
        }
        float rv[32];
        #pragma unroll
        for (int o = 0; o < 32; ++o) {
            float q = __ldg(&rb2[o]);
            #pragma unroll
            for (int j = 0; j < 16; ++j) q += hr[j] * __ldg(&rW2[j * 32 + o]);
            rv[o] = q;
        }
        for (int o4 = 0; o4 < 32; ++o4) {
            float cv[4];
            #pragma unroll
            for (int c = 0; c < 4; ++c) {
                int o = o4 * 4 + c;
                float q = __ldg(&db1[o]);
                #pragma unroll
                for (int j = 0; j < 64; ++j) q += av[j] * __ldg(&dW1[(10 + j) * 128 + o]);
                #pragma unroll
                for (int j = 0; j < 32; ++j) q += rv[j] * __ldg(&dW1[(74 + j) * 128 + o]);
                cv[c] = q;
            }
            g_C[(size_t)o4 * Bn + elem] = make_float4(cv[0], cv[1], cv[2], cv[3]);
        }
    }

    // z0 + output row 0
    float z[10];
    #pragma unroll
    for (int j = 0; j < 10; ++j) z[j] = z0[elem * 10 + j];
    {
        float2* op0 = (float2*)(out + (size_t)elem * 10);
        #pragma unroll
        for (int j = 0; j < 5; ++j) op0[j] = make_float2(z[2 * j], z[2 * j + 1]);
    }

    __syncthreads();   // B tiles + weights visible CTA-wide; steps are warp-synchronous

    // precomputed addresses
    const uint32_t aW   = sbase + A_BYTE + (uint32_t)wid * A_WSTRIDE;        // my warp's A tile
    const uint32_t aRowSts = aW + (uint32_t)lane * 272u;                     // my A row
    const uint32_t grp  = (uint32_t)(lane >> 3);
    const uint32_t aLdmBase = aW + ((grp & 1) * 8 + (uint32_t)(lane & 7)) * 272u + (grp >> 1) * 16u;
    const uint32_t bLdmLane = (uint32_t)(lane & 7) * 272u + grp * 16u;
    float* route = (float*)(smc + ROUTE_BYTE + wid * 32 * 48);
    const float* tsf = (const float*)(smc + TS_BYTE);
    const float4* pC = g_C + elem;

    // ================= SDE integration (warp-synchronous) =================
    for (int s = 0; s < nstep; ++s) {
        const float t  = tsf[s];
        const float dt = tsf[s + 1] - t;
        const float sq = sqrtf(dt);

        ull zp[5];
        #pragma unroll
        for (int j = 0; j < 5; ++j) zp[j] = pack2(z[2 * j], z[2 * j + 1]);

        // ---- h1 row (fp32 preact + tanh.approx) -> bf16 -> A tile ----
        // pipelined g_C reads: ca/cb = rows 2kc,2kc+1; cc/cd = rows 2kc+2,2kc+3
        {
            float4 ca = __ldg(pC);
            float4 cb = __ldg(pC + Bn);
            float4 cc = __ldg(pC + 2 * (size_t)Bn);
            float4 cd = __ldg(pC + 3 * (size_t)Bn);
            for (int kc = 0; kc < 16; ++kc) {
                float cv[8] = {ca.x, ca.y, ca.z, ca.w, cb.x, cb.y, cb.z, cb.w};
                ca = cc; cb = cd;
                if (kc < 14) {
                    cc = __ldg(pC + (2 * kc + 4) * (size_t)Bn);
                    cd = __ldg(pC + (2 * kc + 5) * (size_t)Bn);
                }
                uint32_t a4[4];
                #pragma unroll
                for (int u2 = 0; u2 < 4; ++u2) {
                    float hv[2];
                    #pragma unroll
                    for (int e = 0; e < 2; ++e) {
                        const int k = kc * 8 + u2 * 2 + e;
                        const float4* w1r = (const float4*)(smc + W1_BYTE + k * 64);
                        float4 w0 = w1r[0], w4 = w1r[1], w8 = w1r[2];
                        ull p2 = pack2(cv[u2 * 2 + e], t * w8.z);
                        p2 = ffma2(zp[0], pack2(w0.x, w0.y), p2);
                        p2 = ffma2(zp[1], pack2(w0.z, w0.w), p2);
                        p2 = ffma2(zp[2], pack2(w4.x, w4.y), p2);
                        p2 = ffma2(zp[3], pack2(w4.z, w4.w), p2);
                        p2 = ffma2(zp[4], pack2(w8.x, w8.y), p2);
                        float plo, phi; unpack2(p2, plo, phi);
                        hv[e] = tanh_hw(plo + phi);
                    }
                    a4[u2] = bf16x2_of(hv[0], hv[1]);
                }
                *(uint4*)(smc + (aRowSts - sbase) + kc * 16) =
                    make_uint4(a4[0], a4[1], a4[2], a4[3]);
            }
        }
        __syncwarp();

        // ---- A fragments ----
        uint32_t af[2][8][4];
        #pragma unroll
        for (int mt = 0; mt < 2; ++mt)
            #pragma unroll
            for (int kt = 0; kt < 8; ++kt)
                ldm_x4(af[mt][kt], aLdmBase + (uint32_t)mt * (16 * 272) + (uint32_t)kt * 32);

        // dz accumulators (4 row-slots x 10), db3 added at routing read
        ull dzp[4][5];
        #pragma unroll
        for (int ss = 0; ss < 4; ++ss)
            #pragma unroll
            for (int jj = 0; jj < 5; ++jj) dzp[ss][jj] = pack2(0.0f, 0.0f);

        for (int half = 0; half < 2; ++half) {
            float acc[2][8][4];
            #pragma unroll
            for (int nt = 0; nt < 8; ++nt) {
                float2 d2 = *(const float2*)(smc + DB2_BYTE + (half * 64 + nt * 8 + qc) * 4);
                #pragma unroll
                for (int mt = 0; mt < 2; ++mt) {
                    acc[mt][nt][0] = d2.x; acc[mt][nt][1] = d2.y;
                    acc[mt][nt][2] = d2.x; acc[mt][nt][3] = d2.y;
                }
            }
            for (int pass = 0; pass < 2; ++pass) {
                const uint32_t bb = sbase + (pass ? BLO_BYTE : BHI_BYTE) + bLdmLane
                                  + (uint32_t)(half * 64) * 272u;
                #pragma unroll
                for (int nt = 0; nt < 8; ++nt) {
                    const uint32_t brow = bb + (uint32_t)(nt * 8) * 272u;
                    #pragma unroll
                    for (int ktp = 0; ktp < 4; ++ktp) {
                        uint32_t r[4];
                        ldm_x4(r, brow + (uint32_t)ktp * 64);
                        mma16816(acc[0][nt], af[0][2 * ktp],     r[0], r[1]);
                        mma16816(acc[1][nt], af[1][2 * ktp],     r[0], r[1]);
                        mma16816(acc[0][nt], af[0][2 * ktp + 1], r[2], r[3]);
                        mma16816(acc[1][nt], af[1][2 * ktp + 1], r[2], r[3]);
                    }
                }
            }
            // epilogue for this half: tanh(h2) @ W3 partials
            #pragma unroll
            for (int nt = 0; nt < 8; ++nt) {
                const int cb = half * 64 + nt * 8 + qc;
                const ull* w3a = (const ull*)(smc + W3_BYTE + cb * 48);
                const ull* w3b = (const ull*)(smc + W3_BYTE + (cb + 1) * 48);
                ull wa[5], wb[5];
                #pragma unroll
                for (int jj = 0; jj < 5; ++jj) { wa[jj] = w3a[jj]; wb[jj] = w3b[jj]; }
                #pragma unroll
                for (int mt = 0; mt < 2; ++mt) {
                    float h0 = tanh_acc(acc[mt][nt][0]);
                    float h1 = tanh_acc(acc[mt][nt][1]);
                    float h2 = tanh_acc(acc[mt][nt][2]);
                    float h3 = tanh_acc(acc[mt][nt][3]);
                    ull p0 = pack2(h0, h0), p1 = pack2(h1, h1);
                    ull p2 = pack2(h2, h2), p3 = pack2(h3, h3);
                    #pragma unroll
                    for (int jj = 0; jj < 5; ++jj) {
                        dzp[mt * 2][jj]     = ffma2(p0, wa[jj], dzp[mt * 2][jj]);
                        dzp[mt * 2][jj]     = ffma2(p1, wb[jj], dzp[mt * 2][jj]);
                        dzp[mt * 2 + 1][jj] = ffma2(p2, wa[jj], dzp[mt * 2 + 1][jj]);
                        dzp[mt * 2 + 1][jj] = ffma2(p3, wb[jj], dzp[mt * 2 + 1][jj]);
                    }
                }
            }
        }

        // ---- quad reduce + route dz to owner lane ----
        float dzf[4][10];
        #pragma unroll
        for (int ss = 0; ss < 4; ++ss)
            #pragma unroll
            for (int jj = 0; jj < 5; ++jj)
                unpack2(dzp[ss][jj], dzf[ss][2 * jj], dzf[ss][2 * jj + 1]);
        #pragma unroll
        for (int ss = 0; ss < 4; ++ss)
            #pragma unroll
            for (int j = 0; j < 10; ++j) {
                float v = dzf[ss][j];
                v += __shfl_xor_sync(0xffffffffu, v, 1);
                v += __shfl_xor_sync(0xffffffffu, v, 2);
                dzf[ss][j] = v;
            }
        if ((lane & 3) == 0) {
            const int g = lane >> 2;
            #pragma unroll
            for (int ss = 0; ss < 4; ++ss) {
                const int row = ((ss >> 1) << 4) + ((ss & 1) << 3) + g;
                float2* rp = (float2*)(route + row * 12);
                #pragma unroll
                for (int jj = 0; jj < 5; ++jj)
                    rp[jj] = make_float2(dzf[ss][2 * jj], dzf[ss][2 * jj + 1]);
            }
        }
        __syncwarp();
        float dz[10];
        {
            const float* rp = route + lane * 12;
            const float* d3 = (const float*)(smc + DB3_BYTE);
            #pragma unroll
            for (int j = 0; j < 10; ++j) dz[j] = rp[j] + d3[j];
        }
        __syncwarp();   // protect route buffer before next step's writes

        // ---- diffusion MLP 11 -> 32 -> 10 ----
        ull gvp[5];
        {
            const float2* g2 = (const float2*)(smc + GB2_BYTE);
            #pragma unroll
            for (int jj = 0; jj < 5; ++jj) gvp[jj] = pack2(g2[jj].x, g2[jj].y);
        }
        const float* gb1f = (const float*)(smc + GB1_BYTE);
        #pragma unroll 4
        for (int o = 0; o < 32; ++o) {
            const float4* g1 = (const float4*)(smc + GW1_BYTE + o * 48);
            float4 w0 = g1[0], w4 = g1[1], w8 = g1[2];
            ull p2 = pack2(gb1f[o], t * w8.z);
            p2 = ffma2(zp[0], pack2(w0.x, w0.y), p2);
            p2 = ffma2(zp[1], pack2(w0.z, w0.w), p2);
            p2 = ffma2(zp[2], pack2(w4.x, w4.y), p2);
            p2 = ffma2(zp[3], pack2(w4.z, w4.w), p2);
            p2 = ffma2(zp[4], pack2(w8.x, w8.y), p2);
            float plo, phi; unpack2(p2, plo, phi);
            float q = softplus_(plo + phi);
            ull qq = pack2(q, q);
            const ull* g2w = (const ull*)(smc + GW2_BYTE + o * 48);
            #pragma unroll
            for (int jj = 0; jj < 5; ++jj) gvp[jj] = ffma2(qq, g2w[jj], gvp[jj]);
        }

        // ---- Euler-Maruyama update + stream out ----
        const float2* np = (const float2*)(noise + ((size_t)s * Bn + elem) * 10);
        float2*       op = (float2*)(out + ((size_t)(s + 1) * Bn + elem) * 10);
        #pragma unroll
        for (int j = 0; j < 5; ++j) {
            float glo, ghi; unpack2(gvp[j], glo, ghi);
            float2 e = np[j];
            z[2 * j]     += dz[2 * j]     * dt + glo * sq * e.x;
            z[2 * j + 1] += dz[2 * j + 1] * dt + ghi * sq * e.y;
            op[j] = make_float2(z[2 * j], z[2 * j + 1]);
        }
    }
}

extern "C" void kernel_launch(void* const* d_in, const int* in_sizes, int n_in,
                              void* d_out, int out_size) {
    const float* z0       = (const float*)d_in[0];
    const float* activity = (const float*)d_in[1];
    const float* rest     = (const float*)d_in[2];
    const float* ts       = (const float*)d_in[3];
    const float* noise    = (const float*)d_in[4];
    const float* aW1 = (const float*)d_in[5];
    const float* ab1 = (const float*)d_in[6];
    const float* aW2 = (const float*)d_in[7];
    const float* ab2 = (const float*)d_in[8];
    const float* rW1 = (const float*)d_in[9];
    const float* rb1 = (const float*)d_in[10];
    const float* rW2 = (const float*)d_in[11];
    const float* rb2 = (const float*)d_in[12];
    const float* dW1 = (const float*)d_in[13];
    const float* db1 = (const float*)d_in[14];
    const float* dW2 = (const float*)d_in[15];
    const float* db2 = (const float*)d_in[16];
    const float* dW3 = (const float*)d_in[17];
    const float* db3 = (const float*)d_in[18];
    const float* gW1 = (const float*)d_in[19];
    const float* gb1 = (const float*)d_in[20];
    const float* gW2 = (const float*)d_in[21];
    const float* gb2 = (const float*)d_in[22];

    int B     = in_sizes[0] / 10;
    int nstep = in_sizes[3] - 1;

    cudaFuncSetAttribute(sde_hmma, cudaFuncAttributeMaxDynamicSharedMemorySize,
                         SMEM_BYTES);
    int grid = (B + TPB - 1) / TPB;
    sde_hmma<<<grid, TPB, SMEM_BYTES>>>(
        z0, activity, rest, ts, noise,
        aW1, ab1, aW2, ab2, rW1, rb1, rW2, rb2,
        dW1, db1, dW2, db2, dW3, db3,
        gW1, gb1, gW2, gb2,
        (float*)d_out, B, nstep);
}

// round 7
// speedup vs baseline: 3.3392x; 1.0510x over previous
#include <cuda_runtime.h>
#include <cuda_bf16.h>
#include <cstdint>
#include <cstddef>

#define TPB 256
#define NWARP 8

typedef unsigned long long ull;

// C context scratch: layout Cq[k/4][elem] as float4 (coalesced per-warp reads).
__device__ float4 g_C[32 * 32768];

// ---------------- packed f32x2 (Blackwell FFMA2) ----------------
__device__ __forceinline__ ull ffma2(ull a, ull b, ull c) {
    ull d; asm("fma.rn.f32x2 %0, %1, %2, %3;" : "=l"(d) : "l"(a), "l"(b), "l"(c)); return d;
}
__device__ __forceinline__ ull pack2(float lo, float hi) {
    ull r; asm("mov.b64 %0, {%1, %2};" : "=l"(r) : "f"(lo), "f"(hi)); return r;
}
__device__ __forceinline__ void unpack2(ull v, float& lo, float& hi) {
    asm("mov.b64 {%0, %1}, %2;" : "=f"(lo), "=f"(hi) : "l"(v));
}
__device__ __forceinline__ uint32_t bf16x2_of(float lo, float hi) {
    uint32_t r; asm("cvt.rn.bf16x2.f32 %0, %1, %2;" : "=r"(r) : "f"(hi), "f"(lo)); return r;
}
// ---------------- activations ----------------
__device__ __forceinline__ float tanh_hw(float x) {     // 1 MUFU op
    float y; asm("tanh.approx.f32 %0, %1;" : "=f"(y) : "f"(x)); return y;
}
__device__ __forceinline__ float softplus_(float x) {
    return fmaxf(x, 0.0f) + __logf(1.0f + __expf(-fabsf(x)));
}
// ---------------- tensor-core ops (baseline PTX, no 'a' needed) ----------------
__device__ __forceinline__ void mma16816(float* c, const uint32_t* a, uint32_t b0, uint32_t b1) {
    asm volatile("mma.sync.aligned.m16n8k16.row.col.f32.bf16.bf16.f32 "
        "{%0,%1,%2,%3}, {%4,%5,%6,%7}, {%8,%9}, {%0,%1,%2,%3};"
        : "+f"(c[0]), "+f"(c[1]), "+f"(c[2]), "+f"(c[3])
        : "r"(a[0]), "r"(a[1]), "r"(a[2]), "r"(a[3]), "r"(b0), "r"(b1));
}
__device__ __forceinline__ void ldm_x4(uint32_t* r, uint32_t addr) {
    asm volatile("ldmatrix.sync.aligned.m8n8.x4.shared.b16 {%0,%1,%2,%3}, [%4];"
        : "=r"(r[0]), "=r"(r[1]), "=r"(r[2]), "=r"(r[3]) : "r"(addr));
}
__device__ __forceinline__ uint32_t smem_u32(const void* p) {
    uint32_t a;
    asm("{ .reg .u64 t; cvta.to.shared.u64 t, %1; cvt.u32.u64 %0, t; }" : "=r"(a) : "l"(p));
    return a;
}

// ---------------- SMEM byte layout ----------------
#define A_BYTE     0
#define A_WSTRIDE  (32 * 272)                 // 8704 per warp
#define BHI_BYTE   69632                      // W2^T hi: 128 rows(n) x 128 bf16, stride 272
#define BLO_BYTE   104448                     // W2^T lo
#define W1_BYTE    139264                     // [128][16] floats: w0..w9, wt, pad
#define W3_BYTE    147456                     // [128][12] floats
#define DB2_BYTE   153600                     // [128]
#define GW1_BYTE   154112                     // [32][12]
#define GW2_BYTE   155648                     // [32][12]
#define GB1_BYTE   157184                     // [32]
#define TS_BYTE    157312                     // [128]
#define GB2_BYTE   157824                     // [12]
#define DB3_BYTE   157872                     // [12]
#define ROUTE_BYTE 157920                     // [8 warps][32 rows][12 floats]
#define SMEM_BYTES (157920 + 8 * 32 * 12 * 4) // 170208

__global__ void __launch_bounds__(TPB, 1)
sde_hmma(const float* __restrict__ z0, const float* __restrict__ activity,
         const float* __restrict__ rest, const float* __restrict__ ts,
         const float* __restrict__ noise,
         const float* __restrict__ aW1, const float* __restrict__ ab1,
         const float* __restrict__ aW2, const float* __restrict__ ab2,
         const float* __restrict__ rW1, const float* __restrict__ rb1,
         const float* __restrict__ rW2, const float* __restrict__ rb2,
         const float* __restrict__ dW1, const float* __restrict__ db1,
         const float* __restrict__ dW2, const float* __restrict__ db2,
         const float* __restrict__ dW3, const float* __restrict__ db3,
         const float* __restrict__ gW1, const float* __restrict__ gb1,
         const float* __restrict__ gW2, const float* __restrict__ gb2,
         float* __restrict__ out, int Bn, int nstep)
{
    extern __shared__ char smc[];
    const uint32_t sbase = smem_u32(smc);
    const int tid  = threadIdx.x;
    const int wid  = tid >> 5;
    const int lane = tid & 31;
    const int elem = blockIdx.x * TPB + tid;
    const int qc   = (lane & 3) * 2;          // fragment col pair base

    // ================= one-time staging =================
    for (int i = tid; i < 16384; i += TPB) {
        int k = i >> 7, n = i & 127;
        float w = dW2[i];
        __nv_bfloat16 hi = __float2bfloat16(w);
        __nv_bfloat16 lo = __float2bfloat16(w - __bfloat162float(hi));
        uint32_t off = (uint32_t)n * 272u + (uint32_t)k * 2u;
        *(__nv_bfloat16*)(smc + BHI_BYTE + off) = hi;
        *(__nv_bfloat16*)(smc + BLO_BYTE + off) = lo;
    }
    if (tid < 128) {
        float* w1r = (float*)(smc + W1_BYTE + tid * 64);
        #pragma unroll
        for (int j = 0; j < 10; ++j) w1r[j] = dW1[j * 128 + tid];
        w1r[10] = dW1[106 * 128 + tid];       // t row
        w1r[11] = 0.0f; w1r[12] = 0.0f; w1r[13] = 0.0f; w1r[14] = 0.0f; w1r[15] = 0.0f;
        ((float*)(smc + DB2_BYTE))[tid] = db2[tid];
        float* w3r = (float*)(smc + W3_BYTE + tid * 48);
        #pragma unroll
        for (int j = 0; j < 10; ++j) w3r[j] = dW3[tid * 10 + j];
        w3r[10] = 0.0f; w3r[11] = 0.0f;
    }
    if (tid < 32) {
        float* g1r = (float*)(smc + GW1_BYTE + tid * 48);
        #pragma unroll
        for (int j = 0; j < 10; ++j) g1r[j] = gW1[j * 32 + tid];
        g1r[10] = gW1[10 * 32 + tid];
        g1r[11] = 0.0f;
        float* g2r = (float*)(smc + GW2_BYTE + tid * 48);
        #pragma unroll
        for (int j = 0; j < 10; ++j) g2r[j] = gW2[tid * 10 + j];
        g2r[10] = 0.0f; g2r[11] = 0.0f;
        ((float*)(smc + GB1_BYTE))[tid] = gb1[tid];
    }
    if (tid < 12) {
        ((float*)(smc + GB2_BYTE))[tid] = (tid < 10) ? gb2[tid] : 0.0f;
        ((float*)(smc + DB3_BYTE))[tid] = (tid < 10) ? db3[tid] : 0.0f;
    }
    for (int i = tid; i <= nstep && i < 128; i += TPB)
        ((float*)(smc + TS_BYTE))[i] = ts[i];

    // ---- context encoders -> C[128] -> g_C transposed float4 ----
    {
        float actv[6], rsv[3];
        #pragma unroll
        for (int j = 0; j < 6; ++j) actv[j] = activity[elem * 6 + j];
        #pragma unroll
        for (int j = 0; j < 3; ++j) rsv[j] = rest[elem * 3 + j];
        float ha[32];
        #pragma unroll
        for (int o = 0; o < 32; ++o) {
            float q = __ldg(&ab1[o]);
            #pragma unroll
            for (int j = 0; j < 6; ++j) q += actv[j] * __ldg(&aW1[j * 32 + o]);
            ha[o] = fmaxf(q, 0.0f);
        }
        float av[64];
        #pragma unroll
        for (int o = 0; o < 64; ++o) {
            float q = __ldg(&ab2[o]);
            #pragma unroll
            for (int j = 0; j < 32; ++j) q += ha[j] * __ldg(&aW2[j * 64 + o]);
            av[o] = q;
        }
        float hr[16];
        #pragma unroll
        for (int o = 0; o < 16; ++o) {
            float q = __ldg(&rb1[o]);
            #pragma unroll
            for (int j = 0; j < 3; ++j) q += rsv[j] * __ldg(&rW1[j * 16 + o]);
            hr[o] = fmaxf(q, 0.0f);
        }
        float rv[32];
        #pragma unroll
        for (int o = 0; o < 32; ++o) {
            float q = __ldg(&rb2[o]);
            #pragma unroll
            for (int j = 0; j < 16; ++j) q += hr[j] * __ldg(&rW2[j * 32 + o]);
            rv[o] = q;
        }
        for (int o4 = 0; o4 < 32; ++o4) {
            float cv[4];
            #pragma unroll
            for (int c = 0; c < 4; ++c) {
                int o = o4 * 4 + c;
                float q = __ldg(&db1[o]);
                #pragma unroll
                for (int j = 0; j < 64; ++j) q += av[j] * __ldg(&dW1[(10 + j) * 128 + o]);
                #pragma unroll
                for (int j = 0; j < 32; ++j) q += rv[j] * __ldg(&dW1[(74 + j) * 128 + o]);
                cv[c] = q;
            }
            g_C[(size_t)o4 * Bn + elem] = make_float4(cv[0], cv[1], cv[2], cv[3]);
        }
    }

    // z0 + output row 0
    float z[10];
    #pragma unroll
    for (int j = 0; j < 10; ++j) z[j] = z0[elem * 10 + j];
    {
        float2* op0 = (float2*)(out + (size_t)elem * 10);
        #pragma unroll
        for (int j = 0; j < 5; ++j) op0[j] = make_float2(z[2 * j], z[2 * j + 1]);
    }

    __syncthreads();   // B tiles + weights visible CTA-wide; steps are warp-synchronous

    // precomputed addresses
    const uint32_t aW   = sbase + A_BYTE + (uint32_t)wid * A_WSTRIDE;
    const uint32_t aRowSts = aW + (uint32_t)lane * 272u;
    const uint32_t grp  = (uint32_t)(lane >> 3);
    const uint32_t aLdmBase = aW + ((grp & 1) * 8 + (uint32_t)(lane & 7)) * 272u + (grp >> 1) * 16u;
    const uint32_t bLdmLane = (uint32_t)(lane & 7) * 272u + grp * 16u;
    float* route = (float*)(smc + ROUTE_BYTE + wid * 32 * 48);
    const float* tsf = (const float*)(smc + TS_BYTE);
    const float4* pC = g_C + elem;

    // ================= SDE integration (warp-synchronous) =================
    for (int s = 0; s < nstep; ++s) {
        const float t  = tsf[s];
        const float dt = tsf[s + 1] - t;
        const float sq = sqrtf(dt);

        ull zp[5];
        #pragma unroll
        for (int j = 0; j < 5; ++j) zp[j] = pack2(z[2 * j], z[2 * j + 1]);

        // ---- h1 row (fp32 preact + tanh.approx) -> bf16 -> A tile ----
        {
            float4 ca = __ldg(pC);
            float4 cb = __ldg(pC + Bn);
            float4 cc = __ldg(pC + 2 * (size_t)Bn);
            float4 cd = __ldg(pC + 3 * (size_t)Bn);
            for (int kc = 0; kc < 16; ++kc) {
                float cv[8] = {ca.x, ca.y, ca.z, ca.w, cb.x, cb.y, cb.z, cb.w};
                ca = cc; cb = cd;
                if (kc < 14) {
                    cc = __ldg(pC + (2 * kc + 4) * (size_t)Bn);
                    cd = __ldg(pC + (2 * kc + 5) * (size_t)Bn);
                }
                uint32_t a4[4];
                #pragma unroll
                for (int u2 = 0; u2 < 4; ++u2) {
                    float hv[2];
                    #pragma unroll
                    for (int e = 0; e < 2; ++e) {
                        const int k = kc * 8 + u2 * 2 + e;
                        const float4* w1r = (const float4*)(smc + W1_BYTE + k * 64);
                        float4 w0 = w1r[0], w4 = w1r[1], w8 = w1r[2];
                        ull p2 = pack2(cv[u2 * 2 + e], t * w8.z);
                        p2 = ffma2(zp[0], pack2(w0.x, w0.y), p2);
                        p2 = ffma2(zp[1], pack2(w0.z, w0.w), p2);
                        p2 = ffma2(zp[2], pack2(w4.x, w4.y), p2);
                        p2 = ffma2(zp[3], pack2(w4.z, w4.w), p2);
                        p2 = ffma2(zp[4], pack2(w8.x, w8.y), p2);
                        float plo, phi; unpack2(p2, plo, phi);
                        hv[e] = tanh_hw(plo + phi);
                    }
                    a4[u2] = bf16x2_of(hv[0], hv[1]);
                }
                *(uint4*)(smc + (aRowSts - sbase) + kc * 16) =
                    make_uint4(a4[0], a4[1], a4[2], a4[3]);
            }
        }
        __syncwarp();

        // ---- A fragments ----
        uint32_t af[2][8][4];
        #pragma unroll
        for (int mt = 0; mt < 2; ++mt)
            #pragma unroll
            for (int kt = 0; kt < 8; ++kt)
                ldm_x4(af[mt][kt], aLdmBase + (uint32_t)mt * (16 * 272) + (uint32_t)kt * 32);

        // dz accumulators (4 row-slots x 10), db3 added at routing read
        ull dzp[4][5];
        #pragma unroll
        for (int ss = 0; ss < 4; ++ss)
            #pragma unroll
            for (int jj = 0; jj < 5; ++jj) dzp[ss][jj] = pack2(0.0f, 0.0f);

        #pragma unroll
        for (int half = 0; half < 2; ++half) {
            #pragma unroll
            for (int g4 = 0; g4 < 2; ++g4) {       // n-tiles in groups of 4: low reg peak
                float acc[2][4][4];
                #pragma unroll
                for (int ni = 0; ni < 4; ++ni) {
                    float2 d2 = *(const float2*)(smc + DB2_BYTE +
                                 (half * 64 + (g4 * 4 + ni) * 8 + qc) * 4);
                    #pragma unroll
                    for (int mt = 0; mt < 2; ++mt) {
                        acc[mt][ni][0] = d2.x; acc[mt][ni][1] = d2.y;
                        acc[mt][ni][2] = d2.x; acc[mt][ni][3] = d2.y;
                    }
                }
                #pragma unroll
                for (int pass = 0; pass < 2; ++pass) {
                    const uint32_t bb = sbase + (pass ? BLO_BYTE : BHI_BYTE) + bLdmLane
                                      + (uint32_t)(half * 64) * 272u;
                    #pragma unroll
                    for (int ni = 0; ni < 4; ++ni) {
                        const uint32_t brow = bb + (uint32_t)((g4 * 4 + ni) * 8) * 272u;
                        #pragma unroll
                        for (int ktp = 0; ktp < 4; ++ktp) {
                            uint32_t r[4];
                            ldm_x4(r, brow + (uint32_t)ktp * 64);
                            mma16816(acc[0][ni], af[0][2 * ktp],     r[0], r[1]);
                            mma16816(acc[1][ni], af[1][2 * ktp],     r[0], r[1]);
                            mma16816(acc[0][ni], af[0][2 * ktp + 1], r[2], r[3]);
                            mma16816(acc[1][ni], af[1][2 * ktp + 1], r[2], r[3]);
                        }
                    }
                }
                // epilogue for this n-group: tanh.approx(h2) @ W3 partials
                #pragma unroll
                for (int ni = 0; ni < 4; ++ni) {
                    const int cb = half * 64 + (g4 * 4 + ni) * 8 + qc;
                    const ull* w3a = (const ull*)(smc + W3_BYTE + cb * 48);
                    const ull* w3b = (const ull*)(smc + W3_BYTE + (cb + 1) * 48);
                    ull wa[5], wb[5];
                    #pragma unroll
                    for (int jj = 0; jj < 5; ++jj) { wa[jj] = w3a[jj]; wb[jj] = w3b[jj]; }
                    #pragma unroll
                    for (int mt = 0; mt < 2; ++mt) {
                        float h0 = tanh_hw(acc[mt][ni][0]);
                        float h1 = tanh_hw(acc[mt][ni][1]);
                        float h2 = tanh_hw(acc[mt][ni][2]);
                        float h3 = tanh_hw(acc[mt][ni][3]);
                        ull p0 = pack2(h0, h0), p1 = pack2(h1, h1);
                        ull p2 = pack2(h2, h2), p3 = pack2(h3, h3);
                        #pragma unroll
                        for (int jj = 0; jj < 5; ++jj) {
                            dzp[mt * 2][jj]     = ffma2(p0, wa[jj], dzp[mt * 2][jj]);
                            dzp[mt * 2][jj]     = ffma2(p1, wb[jj], dzp[mt * 2][jj]);
                            dzp[mt * 2 + 1][jj] = ffma2(p2, wa[jj], dzp[mt * 2 + 1][jj]);
                            dzp[mt * 2 + 1][jj] = ffma2(p3, wb[jj], dzp[mt * 2 + 1][jj]);
                        }
                    }
                }
            }
        }

        // ---- quad reduce + route dz to owner lane ----
        float dzf[4][10];
        #pragma unroll
        for (int ss = 0; ss < 4; ++ss)
            #pragma unroll
            for (int jj = 0; jj < 5; ++jj)
                unpack2(dzp[ss][jj], dzf[ss][2 * jj], dzf[ss][2 * jj + 1]);
        #pragma unroll
        for (int ss = 0; ss < 4; ++ss)
            #pragma unroll
            for (int j = 0; j < 10; ++j) {
                float v = dzf[ss][j];
                v += __shfl_xor_sync(0xffffffffu, v, 1);
                v += __shfl_xor_sync(0xffffffffu, v, 2);
                dzf[ss][j] = v;
            }
        if ((lane & 3) == 0) {
            const int g = lane >> 2;
            #pragma unroll
            for (int ss = 0; ss < 4; ++ss) {
                const int row = ((ss >> 1) << 4) + ((ss & 1) << 3) + g;
                float2* rp = (float2*)(route + row * 12);
                #pragma unroll
                for (int jj = 0; jj < 5; ++jj)
                    rp[jj] = make_float2(dzf[ss][2 * jj], dzf[ss][2 * jj + 1]);
            }
        }
        __syncwarp();
        float dz[10];
        {
            const float* rp = route + lane * 12;
            const float* d3 = (const float*)(smc + DB3_BYTE);
            #pragma unroll
            for (int j = 0; j < 10; ++j) dz[j] = rp[j] + d3[j];
        }
        __syncwarp();   // protect route buffer before next step's writes

        // ---- diffusion MLP 11 -> 32 -> 10 ----
        ull gvp[5];
        {
            const float2* g2 = (const float2*)(smc + GB2_BYTE);
            #pragma unroll
            for (int jj = 0; jj < 5; ++jj) gvp[jj] = pack2(g2[jj].x, g2[jj].y);
        }
        const float* gb1f = (const float*)(smc + GB1_BYTE);
        #pragma unroll 4
        for (int o = 0; o < 32; ++o) {
            const float4* g1 = (const float4*)(smc + GW1_BYTE + o * 48);
            float4 w0 = g1[0], w4 = g1[1], w8 = g1[2];
            ull p2 = pack2(gb1f[o], t * w8.z);
            p2 = ffma2(zp[0], pack2(w0.x, w0.y), p2);
            p2 = ffma2(zp[1], pack2(w0.z, w0.w), p2);
            p2 = ffma2(zp[2], pack2(w4.x, w4.y), p2);
            p2 = ffma2(zp[3], pack2(w4.z, w4.w), p2);
            p2 = ffma2(zp[4], pack2(w8.x, w8.y), p2);
            float plo, phi; unpack2(p2, plo, phi);
            float q = softplus_(plo + phi);
            ull qq = pack2(q, q);
            const ull* g2w = (const ull*)(smc + GW2_BYTE + o * 48);
            #pragma unroll
            for (int jj = 0; jj < 5; ++jj) gvp[jj] = ffma2(qq, g2w[jj], gvp[jj]);
        }

        // ---- Euler-Maruyama update + stream out ----
        const float2* np = (const float2*)(noise + ((size_t)s * Bn + elem) * 10);
        float2*       op = (float2*)(out + ((size_t)(s + 1) * Bn + elem) * 10);
        #pragma unroll
        for (int j = 0; j < 5; ++j) {
            float glo, ghi; unpack2(gvp[j], glo, ghi);
            float2 e = np[j];
            z[2 * j]     += dz[2 * j]     * dt + glo * sq * e.x;
            z[2 * j + 1] += dz[2 * j + 1] * dt + ghi * sq * e.y;
            op[j] = make_float2(z[2 * j], z[2 * j + 1]);
        }
    }
}

extern "C" void kernel_launch(void* const* d_in, const int* in_sizes, int n_in,
                              void* d_out, int out_size) {
    const float* z0       = (const float*)d_in[0];
    const float* activity = (const float*)d_in[1];
    const float* rest     = (const float*)d_in[2];
    const float* ts       = (const float*)d_in[3];
    const float* noise    = (const float*)d_in[4];
    const float* aW1 = (const float*)d_in[5];
    const float* ab1 = (const float*)d_in[6];
    const float* aW2 = (const float*)d_in[7];
    const float* ab2 = (const float*)d_in[8];
    const float* rW1 = (const float*)d_in[9];
    const float* rb1 = (const float*)d_in[10];
    const float* rW2 = (const float*)d_in[11];
    const float* rb2 = (const float*)d_in[12];
    const float* dW1 = (const float*)d_in[13];
    const float* db1 = (const float*)d_in[14];
    const float* dW2 = (const float*)d_in[15];
    const float* db2 = (const float*)d_in[16];
    const float* dW3 = (const float*)d_in[17];
    const float* db3 = (const float*)d_in[18];
    const float* gW1 = (const float*)d_in[19];
    const float* gb1 = (const float*)d_in[20];
    const float* gW2 = (const float*)d_in[21];
    const float* gb2 = (const float*)d_in[22];

    int B     = in_sizes[0] / 10;
    int nstep = in_sizes[3] - 1;

    cudaFuncSetAttribute(sde_hmma, cudaFuncAttributeMaxDynamicSharedMemorySize,
                         SMEM_BYTES);
    int grid = (B + TPB - 1) / TPB;
    sde_hmma<<<grid, TPB, SMEM_BYTES>>>(
        z0, activity, rest, ts, noise,
        aW1, ab1, aW2, ab2, rW1, rb1, rW2, rb2,
        dW1, db1, dW2, db2, dW3, db3,
        gW1, gb1, gW2, gb2,
        (float*)d_out, B, nstep);
}

// round 8
// speedup vs baseline: 4.1346x; 1.2382x over previous
#include <cuda_runtime.h>
#include <cuda_bf16.h>
#include <cstdint>
#include <cstddef>

#define TPB 224
#define NWARP 7

typedef unsigned long long ull;

// C context: [col/4][elem] float4 (intermediate), and fragment-packed per warp.
__device__ float4 g_C[32 * 32768];
__device__ float4 g_Cf[1056 * 32 * 32];   // [gwarp][mt*16+nt][lane]

// ---------------- packed f32x2 ----------------
__device__ __forceinline__ ull ffma2(ull a, ull b, ull c) {
    ull d; asm("fma.rn.f32x2 %0, %1, %2, %3;" : "=l"(d) : "l"(a), "l"(b), "l"(c)); return d;
}
__device__ __forceinline__ ull pack2(float lo, float hi) {
    ull r; asm("mov.b64 %0, {%1, %2};" : "=l"(r) : "f"(lo), "f"(hi)); return r;
}
__device__ __forceinline__ void unpack2(ull v, float& lo, float& hi) {
    asm("mov.b64 {%0, %1}, %2;" : "=f"(lo), "=f"(hi) : "l"(v));
}
__device__ __forceinline__ uint32_t bf16x2_of(float lo, float hi) {
    uint32_t r; asm("cvt.rn.bf16x2.f32 %0, %1, %2;" : "=r"(r) : "f"(hi), "f"(lo)); return r;
}
__device__ __forceinline__ float tanh_hw(float x) {
    float y; asm("tanh.approx.f32 %0, %1;" : "=f"(y) : "f"(x)); return y;
}
__device__ __forceinline__ float softplus_(float x) {
    return fmaxf(x, 0.0f) + __logf(1.0f + __expf(-fabsf(x)));
}
__device__ __forceinline__ void mma16816(float* c, const uint32_t* a, uint32_t b0, uint32_t b1) {
    asm volatile("mma.sync.aligned.m16n8k16.row.col.f32.bf16.bf16.f32 "
        "{%0,%1,%2,%3}, {%4,%5,%6,%7}, {%8,%9}, {%0,%1,%2,%3};"
        : "+f"(c[0]), "+f"(c[1]), "+f"(c[2]), "+f"(c[3])
        : "r"(a[0]), "r"(a[1]), "r"(a[2]), "r"(a[3]), "r"(b0), "r"(b1));
}
__device__ __forceinline__ void ldm_x4(uint32_t* r, uint32_t addr) {
    asm volatile("ldmatrix.sync.aligned.m8n8.x4.shared.b16 {%0,%1,%2,%3}, [%4];"
        : "=r"(r[0]), "=r"(r[1]), "=r"(r[2]), "=r"(r[3]) : "r"(addr));
}
__device__ __forceinline__ uint32_t smem_u32(const void* p) {
    uint32_t a;
    asm("{ .reg .u64 t; cvta.to.shared.u64 t, %1; cvt.u32.u64 %0, t; }" : "=r"(a) : "l"(p));
    return a;
}

// ---------------- SMEM byte layout ----------------
#define ZBUF_BYTE  0                       // 7 warps x 32 rows x 80B
#define W1T_BYTE   17920                   // 128 n-rows x 80B (32 bf16 k: hi|lo|hi|0)
#define ROUTE_BYTE 28160                   // 7 x 32 x 48B
#define DB2_BYTE   38912                   // 128 f
#define WT_BYTE    39424                   // 128 f (t-row of dW1, fp32)
#define W3P_BYTE   39936                   // [128][12] f
#define GW1_BYTE   46080                   // [32][12] f
#define GW2_BYTE   47616                   // [32][12] f
#define GB1_BYTE   49152                   // 32 f
#define TS_BYTE    49280                   // 128 f
#define GB2_BYTE   49792                   // 16 f
#define DB3_BYTE   49856                   // 16 f
#define BHI_BYTE   49920                   // W2^T hi: 128 x 272B
#define BLO_BYTE   84736                   // W2^T lo
#define SMEM_BYTES 119552

__global__ void __launch_bounds__(TPB, 1)
sde_hmma(const float* __restrict__ z0, const float* __restrict__ activity,
         const float* __restrict__ rest, const float* __restrict__ ts,
         const float* __restrict__ noise,
         const float* __restrict__ aW1, const float* __restrict__ ab1,
         const float* __restrict__ aW2, const float* __restrict__ ab2,
         const float* __restrict__ rW1, const float* __restrict__ rb1,
         const float* __restrict__ rW2, const float* __restrict__ rb2,
         const float* __restrict__ dW1, const float* __restrict__ db1,
         const float* __restrict__ dW2, const float* __restrict__ db2,
         const float* __restrict__ dW3, const float* __restrict__ db3,
         const float* __restrict__ gW1, const float* __restrict__ gb1,
         const float* __restrict__ gW2, const float* __restrict__ gb2,
         float* __restrict__ out, int Bn, int nstep)
{
    extern __shared__ char smc[];
    const uint32_t sbase = smem_u32(smc);
    const int tid  = threadIdx.x;
    const int wid  = tid >> 5;
    const int lane = tid & 31;
    const int gid  = lane >> 2;
    const int tid4 = lane & 3;
    const int qc   = tid4 * 2;
    const int elem = blockIdx.x * TPB + tid;
    const int elemBase = blockIdx.x * TPB + wid * 32;
    const bool active = (elemBase < Bn);            // warp-uniform (Bn % 32 == 0)
    const int gw = blockIdx.x * NWARP + wid;

    // ================= one-time staging =================
    // W2^T hi/lo bf16: BT[n][k] at n*272 + 2k
    for (int i = tid; i < 16384; i += TPB) {
        int k = i >> 7, n = i & 127;
        float w = dW2[i];
        __nv_bfloat16 hi = __float2bfloat16(w);
        __nv_bfloat16 lo = __float2bfloat16(w - __bfloat162float(hi));
        uint32_t off = (uint32_t)n * 272u + (uint32_t)k * 2u;
        *(__nv_bfloat16*)(smc + BHI_BYTE + off) = hi;
        *(__nv_bfloat16*)(smc + BLO_BYTE + off) = lo;
    }
    if (tid < 128) {
        // W1T row n=tid: k0..9 = hi(dW1[j][n]), k10..19 = lo, k20..29 = hi, rest 0
        __nv_bfloat16* r = (__nv_bfloat16*)(smc + W1T_BYTE + tid * 80);
        #pragma unroll
        for (int k = 0; k < 40; ++k) r[k] = __float2bfloat16(0.0f);
        #pragma unroll
        for (int j = 0; j < 10; ++j) {
            float w = dW1[j * 128 + tid];
            __nv_bfloat16 hi = __float2bfloat16(w);
            __nv_bfloat16 lo = __float2bfloat16(w - __bfloat162float(hi));
            r[j] = hi; r[10 + j] = lo; r[20 + j] = hi;
        }
        ((float*)(smc + WT_BYTE))[tid]  = dW1[106 * 128 + tid];
        ((float*)(smc + DB2_BYTE))[tid] = db2[tid];
        float* w3r = (float*)(smc + W3P_BYTE + tid * 48);
        #pragma unroll
        for (int j = 0; j < 10; ++j) w3r[j] = dW3[tid * 10 + j];
        w3r[10] = 0.0f; w3r[11] = 0.0f;
    }
    if (tid < 32) {
        float* g1r = (float*)(smc + GW1_BYTE + tid * 48);
        #pragma unroll
        for (int j = 0; j < 10; ++j) g1r[j] = gW1[j * 32 + tid];
        g1r[10] = gW1[10 * 32 + tid];
        g1r[11] = 0.0f;
        float* g2r = (float*)(smc + GW2_BYTE + tid * 48);
        #pragma unroll
        for (int j = 0; j < 10; ++j) g2r[j] = gW2[tid * 10 + j];
        g2r[10] = 0.0f; g2r[11] = 0.0f;
        ((float*)(smc + GB1_BYTE))[tid] = gb1[tid];
    }
    if (tid < 16) {
        ((float*)(smc + GB2_BYTE))[tid] = (tid < 10) ? gb2[tid] : 0.0f;
        ((float*)(smc + DB3_BYTE))[tid] = (tid < 10) ? db3[tid] : 0.0f;
    }
    for (int i = tid; i <= nstep && i < 128; i += TPB)
        ((float*)(smc + TS_BYTE))[i] = ts[i];

    // ---- context encoders -> C[128] -> g_C [col4][elem] ----
    if (elem < Bn) {
        float actv[6], rsv[3];
        #pragma unroll
        for (int j = 0; j < 6; ++j) actv[j] = activity[elem * 6 + j];
        #pragma unroll
        for (int j = 0; j < 3; ++j) rsv[j] = rest[elem * 3 + j];
        float ha[32];
        #pragma unroll
        for (int o = 0; o < 32; ++o) {
            float q = __ldg(&ab1[o]);
            #pragma unroll
            for (int j = 0; j < 6; ++j) q += actv[j] * __ldg(&aW1[j * 32 + o]);
            ha[o] = fmaxf(q, 0.0f);
        }
        float av[64];
        #pragma unroll
        for (int o = 0; o < 64; ++o) {
            float q = __ldg(&ab2[o]);
            #pragma unroll
            for (int j = 0; j < 32; ++j) q += ha[j] * __ldg(&aW2[j * 64 + o]);
            av[o] = q;
        }
        float hr[16];
        #pragma unroll
        for (int o = 0; o < 16; ++o) {
            float q = __ldg(&rb1[o]);
            #pragma unroll
            for (int j = 0; j < 3; ++j) q += rsv[j] * __ldg(&rW1[j * 16 + o]);
            hr[o] = fmaxf(q, 0.0f);
        }
        float rv[32];
        #pragma unroll
        for (int o = 0; o < 32; ++o) {
            float q = __ldg(&rb2[o]);
            #pragma unroll
            for (int j = 0; j < 16; ++j) q += hr[j] * __ldg(&rW2[j * 32 + o]);
            rv[o] = q;
        }
        for (int o4 = 0; o4 < 32; ++o4) {
            float cv[4];
            #pragma unroll
            for (int c = 0; c < 4; ++c) {
                int o = o4 * 4 + c;
                float q = __ldg(&db1[o]);
                #pragma unroll
                for (int j = 0; j < 64; ++j) q += av[j] * __ldg(&dW1[(10 + j) * 128 + o]);
                #pragma unroll
                for (int j = 0; j < 32; ++j) q += rv[j] * __ldg(&dW1[(74 + j) * 128 + o]);
                cv[c] = q;
            }
            g_C[(size_t)o4 * Bn + elem] = make_float4(cv[0], cv[1], cv[2], cv[3]);
        }
    }
    __syncthreads();   // g_C visible CTA-wide; smem staged

    float z[10];
    if (active) {
        // ---- repack C into fragment layout g_Cf ----
        #pragma unroll
        for (int mt = 0; mt < 2; ++mt)
            for (int nt = 0; nt < 16; ++nt) {
                int R0 = elemBase + mt * 16 + gid;
                int o4 = 2 * nt + (tid4 >> 1);
                float4 v0 = g_C[(size_t)o4 * Bn + R0];
                float4 v1 = g_C[(size_t)o4 * Bn + R0 + 8];
                float4 fr;
                if (tid4 & 1) { fr.x = v0.z; fr.y = v0.w; fr.z = v1.z; fr.w = v1.w; }
                else          { fr.x = v0.x; fr.y = v0.y; fr.z = v1.x; fr.w = v1.y; }
                g_Cf[((size_t)gw * 32 + mt * 16 + nt) * 32 + lane] = fr;
            }
        // z0 + output row 0
        #pragma unroll
        for (int j = 0; j < 10; ++j) z[j] = z0[elem * 10 + j];
        float2* op0 = (float2*)(out + (size_t)elem * 10);
        #pragma unroll
        for (int j = 0; j < 5; ++j) op0[j] = make_float2(z[2 * j], z[2 * j + 1]);
    }
    if (!active) return;    // no further __syncthreads

    // precomputed addresses
    const uint32_t zwarp = sbase + ZBUF_BYTE + (uint32_t)wid * (32 * 80);
    const uint32_t zaL   = zwarp + (uint32_t)(lane & 15) * 80u + ((uint32_t)(lane >> 4) & 1u) * 16u;
    const uint32_t w1L   = sbase + W1T_BYTE + (uint32_t)(lane & 7) * 80u
                         + (((uint32_t)lane >> 3) & 1u) * 16u + (((uint32_t)lane >> 4) & 1u) * 640u;
    const uint32_t bLdmLane = (uint32_t)(lane & 7) * 272u + ((uint32_t)lane >> 3) * 16u;
    float* route = (float*)(smc + ROUTE_BYTE + wid * 32 * 48);
    const float* tsf = (const float*)(smc + TS_BYTE);
    const float4* cfp = &g_Cf[(size_t)gw * 32 * 32 + lane];

    // ================= SDE integration (warp-synchronous) =================
    for (int s = 0; s < nstep; ++s) {
        const float t  = tsf[s];
        const float dt = tsf[s + 1] - t;
        const float sq = sqrtf(dt);

        // ---- z-aug row: [z_hi | z_hi | z_lo | 0] as 16 bf16x2 ----
        {
            unsigned short hs[10]; float zl[10];
            #pragma unroll
            for (int j = 0; j < 10; ++j) {
                __nv_bfloat16 h = __float2bfloat16(z[j]);
                hs[j] = __bfloat16_as_ushort(h);
                zl[j] = z[j] - __bfloat162float(h);
            }
            uint32_t p[16];
            #pragma unroll
            for (int i = 0; i < 5; ++i) {
                p[i] = (uint32_t)hs[2 * i] | ((uint32_t)hs[2 * i + 1] << 16);
                p[5 + i] = p[i];
                p[10 + i] = bf16x2_of(zl[2 * i], zl[2 * i + 1]);
            }
            p[15] = 0u;
            uint32_t dst = zwarp + (uint32_t)lane * 80u;
            asm volatile("st.shared.v4.b32 [%0], {%1,%2,%3,%4};" :: "r"(dst),
                "r"(p[0]), "r"(p[1]), "r"(p[2]), "r"(p[3]));
            asm volatile("st.shared.v4.b32 [%0], {%1,%2,%3,%4};" :: "r"(dst + 16),
                "r"(p[4]), "r"(p[5]), "r"(p[6]), "r"(p[7]));
            asm volatile("st.shared.v4.b32 [%0], {%1,%2,%3,%4};" :: "r"(dst + 32),
                "r"(p[8]), "r"(p[9]), "r"(p[10]), "r"(p[11]));
            asm volatile("st.shared.v4.b32 [%0], {%1,%2,%3,%4};" :: "r"(dst + 48),
                "r"(p[12]), "r"(p[13]), "r"(p[14]), "r"(p[15]));
        }
        __syncwarp();

        uint32_t za[2][2][4];
        #pragma unroll
        for (int mt = 0; mt < 2; ++mt)
            #pragma unroll
            for (int ks = 0; ks < 2; ++ks)
                ldm_x4(za[mt][ks], zaL + (uint32_t)mt * 1280u + (uint32_t)ks * 32u);

        // ---- GEMM1: h1 = tanh(zaug @ W1T + C + t*wt) -> A-frags in registers ----
        uint32_t af[2][8][4];
        #pragma unroll
        for (int mt = 0; mt < 2; ++mt) {
            float a1[16][4];
            #pragma unroll
            for (int nt = 0; nt < 16; ++nt) {
                float4 cf = __ldg(cfp + (mt * 16 + nt) * 32);
                float2 w2 = *(const float2*)(smc + WT_BYTE + (nt * 8 + qc) * 4);
                a1[nt][0] = fmaf(t, w2.x, cf.x);
                a1[nt][1] = fmaf(t, w2.y, cf.y);
                a1[nt][2] = fmaf(t, w2.x, cf.z);
                a1[nt][3] = fmaf(t, w2.y, cf.w);
            }
            #pragma unroll
            for (int ks = 0; ks < 2; ++ks)
                #pragma unroll
                for (int i = 0; i < 8; ++i) {
                    uint32_t bw[4];
                    ldm_x4(bw, w1L + (uint32_t)i * 1280u + (uint32_t)ks * 32u);
                    mma16816(a1[2 * i],     za[mt][ks], bw[0], bw[1]);
                    mma16816(a1[2 * i + 1], za[mt][ks], bw[2], bw[3]);
                }
            #pragma unroll
            for (int kt = 0; kt < 8; ++kt) {
                af[mt][kt][0] = bf16x2_of(tanh_hw(a1[2 * kt][0]),     tanh_hw(a1[2 * kt][1]));
                af[mt][kt][1] = bf16x2_of(tanh_hw(a1[2 * kt][2]),     tanh_hw(a1[2 * kt][3]));
                af[mt][kt][2] = bf16x2_of(tanh_hw(a1[2 * kt + 1][0]), tanh_hw(a1[2 * kt + 1][1]));
                af[mt][kt][3] = bf16x2_of(tanh_hw(a1[2 * kt + 1][2]), tanh_hw(a1[2 * kt + 1][3]));
            }
        }

        // ---- GEMM2 (hi+lo) + scalar epilogue ----
        ull dzp[4][5];
        #pragma unroll
        for (int ss = 0; ss < 4; ++ss)
            #pragma unroll
            for (int jj = 0; jj < 5; ++jj) dzp[ss][jj] = pack2(0.0f, 0.0f);

        #pragma unroll
        for (int ng = 0; ng < 4; ++ng) {
            float acc[2][4][4];
            #pragma unroll
            for (int ni = 0; ni < 4; ++ni) {
                float2 d2 = *(const float2*)(smc + DB2_BYTE + ((ng * 4 + ni) * 8 + qc) * 4);
                #pragma unroll
                for (int mt = 0; mt < 2; ++mt) {
                    acc[mt][ni][0] = d2.x; acc[mt][ni][1] = d2.y;
                    acc[mt][ni][2] = d2.x; acc[mt][ni][3] = d2.y;
                }
            }
            #pragma unroll
            for (int pass = 0; pass < 2; ++pass) {
                const uint32_t bb = sbase + (pass ? BLO_BYTE : BHI_BYTE) + bLdmLane;
                #pragma unroll
                for (int ni = 0; ni < 4; ++ni) {
                    const uint32_t brow = bb + (uint32_t)((ng * 4 + ni) * 8) * 272u;
                    #pragma unroll
                    for (int ktp = 0; ktp < 4; ++ktp) {
                        uint32_t r[4];
                        ldm_x4(r, brow + (uint32_t)ktp * 64u);
                        mma16816(acc[0][ni], af[0][2 * ktp],     r[0], r[1]);
                        mma16816(acc[1][ni], af[1][2 * ktp],     r[0], r[1]);
                        mma16816(acc[0][ni], af[0][2 * ktp + 1], r[2], r[3]);
                        mma16816(acc[1][ni], af[1][2 * ktp + 1], r[2], r[3]);
                    }
                }
            }
            #pragma unroll
            for (int ni = 0; ni < 4; ++ni) {
                const int cb = (ng * 4 + ni) * 8 + qc;
                const ull* w3a = (const ull*)(smc + W3P_BYTE + cb * 48);
                const ull* w3b = (const ull*)(smc + W3P_BYTE + (cb + 1) * 48);
                ull wa[5], wb[5];
                #pragma unroll
                for (int jj = 0; jj < 5; ++jj) { wa[jj] = w3a[jj]; wb[jj] = w3b[jj]; }
                #pragma unroll
                for (int mt = 0; mt < 2; ++mt) {
                    float h0 = tanh_hw(acc[mt][ni][0]);
                    float h1 = tanh_hw(acc[mt][ni][1]);
                    float h2 = tanh_hw(acc[mt][ni][2]);
                    float h3 = tanh_hw(acc[mt][ni][3]);
                    ull p0 = pack2(h0, h0), p1 = pack2(h1, h1);
                    ull p2 = pack2(h2, h2), p3 = pack2(h3, h3);
                    #pragma unroll
                    for (int jj = 0; jj < 5; ++jj) {
                        dzp[mt * 2][jj]     = ffma2(p0, wa[jj], dzp[mt * 2][jj]);
                        dzp[mt * 2][jj]     = ffma2(p1, wb[jj], dzp[mt * 2][jj]);
                        dzp[mt * 2 + 1][jj] = ffma2(p2, wa[jj], dzp[mt * 2 + 1][jj]);
                        dzp[mt * 2 + 1][jj] = ffma2(p3, wb[jj], dzp[mt * 2 + 1][jj]);
                    }
                }
            }
        }

        // ---- quad reduce + route dz to owner lane ----
        float dzf[4][10];
        #pragma unroll
        for (int ss = 0; ss < 4; ++ss)
            #pragma unroll
            for (int jj = 0; jj < 5; ++jj)
                unpack2(dzp[ss][jj], dzf[ss][2 * jj], dzf[ss][2 * jj + 1]);
        #pragma unroll
        for (int ss = 0; ss < 4; ++ss)
            #pragma unroll
            for (int j = 0; j < 10; ++j) {
                float v = dzf[ss][j];
                v += __shfl_xor_sync(0xffffffffu, v, 1);
                v += __shfl_xor_sync(0xffffffffu, v, 2);
                dzf[ss][j] = v;
            }
        if (tid4 == 0) {
            #pragma unroll
            for (int ss = 0; ss < 4; ++ss) {
                const int row = ((ss >> 1) << 4) + ((ss & 1) << 3) + gid;
                float2* rp = (float2*)(route + row * 12);
                #pragma unroll
                for (int jj = 0; jj < 5; ++jj)
                    rp[jj] = make_float2(dzf[ss][2 * jj], dzf[ss][2 * jj + 1]);
            }
        }
        __syncwarp();
        float dz[10];
        {
            const float* rp = route + lane * 12;
            const float* d3 = (const float*)(smc + DB3_BYTE);
            #pragma unroll
            for (int j = 0; j < 10; ++j) dz[j] = rp[j] + d3[j];
        }
        __syncwarp();

        // ---- diffusion MLP 11 -> 32 -> 10 ----
        ull zp[5];
        #pragma unroll
        for (int j = 0; j < 5; ++j) zp[j] = pack2(z[2 * j], z[2 * j + 1]);
        ull gvp[5];
        {
            const float2* g2 = (const float2*)(smc + GB2_BYTE);
            #pragma unroll
            for (int jj = 0; jj < 5; ++jj) gvp[jj] = pack2(g2[jj].x, g2[jj].y);
        }
        const float* gb1f = (const float*)(smc + GB1_BYTE);
        #pragma unroll 4
        for (int o = 0; o < 32; ++o) {
            const float4* g1 = (const float4*)(smc + GW1_BYTE + o * 48);
            float4 w0 = g1[0], w4 = g1[1], w8 = g1[2];
            ull p2 = pack2(gb1f[o], t * w8.z);
            p2 = ffma2(zp[0], pack2(w0.x, w0.y), p2);
            p2 = ffma2(zp[1], pack2(w0.z, w0.w), p2);
            p2 = ffma2(zp[2], pack2(w4.x, w4.y), p2);
            p2 = ffma2(zp[3], pack2(w4.z, w4.w), p2);
            p2 = ffma2(zp[4], pack2(w8.x, w8.y), p2);
            float plo, phi; unpack2(p2, plo, phi);
            float q = softplus_(plo + phi);
            ull qq = pack2(q, q);
            const ull* g2w = (const ull*)(smc + GW2_BYTE + o * 48);
            #pragma unroll
            for (int jj = 0; jj < 5; ++jj) gvp[jj] = ffma2(qq, g2w[jj], gvp[jj]);
        }

        // ---- Euler-Maruyama update + stream out ----
        const float2* np = (const float2*)(noise + ((size_t)s * Bn + elem) * 10);
        float2*       op = (float2*)(out + ((size_t)(s + 1) * Bn + elem) * 10);
        #pragma unroll
        for (int j = 0; j < 5; ++j) {
            float glo, ghi; unpack2(gvp[j], glo, ghi);
            float2 e = np[j];
            z[2 * j]     += dz[2 * j]     * dt + glo * sq * e.x;
            z[2 * j + 1] += dz[2 * j + 1] * dt + ghi * sq * e.y;
            op[j] = make_float2(z[2 * j], z[2 * j + 1]);
        }
    }
}

extern "C" void kernel_launch(void* const* d_in, const int* in_sizes, int n_in,
                              void* d_out, int out_size) {
    const float* z0       = (const float*)d_in[0];
    const float* activity = (const float*)d_in[1];
    const float* rest     = (const float*)d_in[2];
    const float* ts       = (const float*)d_in[3];
    const float* noise    = (const float*)d_in[4];
    const float* aW1 = (const float*)d_in[5];
    const float* ab1 = (const float*)d_in[6];
    const float* aW2 = (const float*)d_in[7];
    const float* ab2 = (const float*)d_in[8];
    const float* rW1 = (const float*)d_in[9];
    const float* rb1 = (const float*)d_in[10];
    const float* rW2 = (const float*)d_in[11];
    const float* rb2 = (const float*)d_in[12];
    const float* dW1 = (const float*)d_in[13];
    const float* db1 = (const float*)d_in[14];
    const float* dW2 = (const float*)d_in[15];
    const float* db2 = (const float*)d_in[16];
    const float* dW3 = (const float*)d_in[17];
    const float* db3 = (const float*)d_in[18];
    const float* gW1 = (const float*)d_in[19];
    const float* gb1 = (const float*)d_in[20];
    const float* gW2 = (const float*)d_in[21];
    const float* gb2 = (const float*)d_in[22];

    int B     = in_sizes[0] / 10;
    int nstep = in_sizes[3] - 1;

    cudaFuncSetAttribute(sde_hmma, cudaFuncAttributeMaxDynamicSharedMemorySize,
                         SMEM_BYTES);
    int grid = (B + TPB - 1) / TPB;
    sde_hmma<<<grid, TPB, SMEM_BYTES>>>(
        z0, activity, rest, ts, noise,
        aW1, ab1, aW2, ab2, rW1, rb1, rW2, rb2,
        dW1, db1, dW2, db2, dW3, db3,
        gW1, gb1, gW2, gb2,
        (float*)d_out, B, nstep);
}

// round 9
// speedup vs baseline: 4.1390x; 1.0011x over previous
#include <cuda_runtime.h>
#include <cuda_bf16.h>
#include <cstdint>
#include <cstddef>

#define TPB 224
#define NWARP 7

typedef unsigned long long ull;

// C context: [col/4][elem] float4 (intermediate), and fragment-packed per warp.
__device__ float4 g_C[32 * 32768];
__device__ float4 g_Cf[1056 * 32 * 32];   // [gwarp][mt*16+nt][lane]

// ---------------- packed f32x2 ----------------
__device__ __forceinline__ ull ffma2(ull a, ull b, ull c) {
    ull d; asm("fma.rn.f32x2 %0, %1, %2, %3;" : "=l"(d) : "l"(a), "l"(b), "l"(c)); return d;
}
__device__ __forceinline__ ull pack2(float lo, float hi) {
    ull r; asm("mov.b64 %0, {%1, %2};" : "=l"(r) : "f"(lo), "f"(hi)); return r;
}
__device__ __forceinline__ void unpack2(ull v, float& lo, float& hi) {
    asm("mov.b64 {%0, %1}, %2;" : "=f"(lo), "=f"(hi) : "l"(v));
}
__device__ __forceinline__ uint32_t bf16x2_of(float lo, float hi) {
    uint32_t r; asm("cvt.rn.bf16x2.f32 %0, %1, %2;" : "=r"(r) : "f"(hi), "f"(lo)); return r;
}
__device__ __forceinline__ float tanh_hw(float x) {
    float y; asm("tanh.approx.f32 %0, %1;" : "=f"(y) : "f"(x)); return y;
}
__device__ __forceinline__ float softplus_(float x) {
    return fmaxf(x, 0.0f) + __logf(1.0f + __expf(-fabsf(x)));
}
__device__ __forceinline__ void mma16816(float* c, const uint32_t* a, uint32_t b0, uint32_t b1) {
    asm volatile("mma.sync.aligned.m16n8k16.row.col.f32.bf16.bf16.f32 "
        "{%0,%1,%2,%3}, {%4,%5,%6,%7}, {%8,%9}, {%0,%1,%2,%3};"
        : "+f"(c[0]), "+f"(c[1]), "+f"(c[2]), "+f"(c[3])
        : "r"(a[0]), "r"(a[1]), "r"(a[2]), "r"(a[3]), "r"(b0), "r"(b1));
}
__device__ __forceinline__ void ldm_x4(uint32_t* r, uint32_t addr) {
    asm volatile("ldmatrix.sync.aligned.m8n8.x4.shared.b16 {%0,%1,%2,%3}, [%4];"
        : "=r"(r[0]), "=r"(r[1]), "=r"(r[2]), "=r"(r[3]) : "r"(addr));
}
__device__ __forceinline__ uint32_t smem_u32(const void* p) {
    uint32_t a;
    asm("{ .reg .u64 t; cvta.to.shared.u64 t, %1; cvt.u32.u64 %0, t; }" : "=r"(a) : "l"(p));
    return a;
}

// ---------------- SMEM byte layout ----------------
#define ZBUF_BYTE  0                       // 7 warps x 32 rows x 80B
#define W1T_BYTE   17920                   // 128 n-rows x 80B (32 bf16 k: hi|lo|hi|0)
#define ROUTE_BYTE 28160                   // 7 x 32 x 48B
#define DB2_BYTE   38912                   // 128 f
#define WT_BYTE    39424                   // 128 f (t-row of dW1, fp32)
#define W3P_BYTE   39936                   // [128][12] f
#define GW1_BYTE   46080                   // [32][12] f
#define GW2_BYTE   47616                   // [32][12] f
#define GB1_BYTE   49152                   // 32 f
#define TS_BYTE    49280                   // 128 f
#define GB2_BYTE   49792                   // 16 f
#define DB3_BYTE   49856                   // 16 f
#define BHI_BYTE   49920                   // W2^T hi: 128 x 272B
#define BLO_BYTE   84736                   // W2^T lo
#define SMEM_BYTES 119552

__global__ void __launch_bounds__(TPB, 1)
sde_hmma(const float* __restrict__ z0, const float* __restrict__ activity,
         const float* __restrict__ rest, const float* __restrict__ ts,
         const float* __restrict__ noise,
         const float* __restrict__ aW1, const float* __restrict__ ab1,
         const float* __restrict__ aW2, const float* __restrict__ ab2,
         const float* __restrict__ rW1, const float* __restrict__ rb1,
         const float* __restrict__ rW2, const float* __restrict__ rb2,
         const float* __restrict__ dW1, const float* __restrict__ db1,
         const float* __restrict__ dW2, const float* __restrict__ db2,
         const float* __restrict__ dW3, const float* __restrict__ db3,
         const float* __restrict__ gW1, const float* __restrict__ gb1,
         const float* __restrict__ gW2, const float* __restrict__ gb2,
         float* __restrict__ out, int Bn, int nstep)
{
    extern __shared__ char smc[];
    const uint32_t sbase = smem_u32(smc);
    const int tid  = threadIdx.x;
    const int wid  = tid >> 5;
    const int lane = tid & 31;
    const int gid  = lane >> 2;
    const int tid4 = lane & 3;
    const int qc   = tid4 * 2;
    const int elem = blockIdx.x * TPB + tid;
    const int elemBase = blockIdx.x * TPB + wid * 32;
    const bool active = (elemBase < Bn);            // warp-uniform (Bn % 32 == 0)
    const int gw = blockIdx.x * NWARP + wid;

    // ================= one-time staging =================
    // W2^T hi/lo bf16: BT[n][k] at n*272 + 2k
    for (int i = tid; i < 16384; i += TPB) {
        int k = i >> 7, n = i & 127;
        float w = dW2[i];
        __nv_bfloat16 hi = __float2bfloat16(w);
        __nv_bfloat16 lo = __float2bfloat16(w - __bfloat162float(hi));
        uint32_t off = (uint32_t)n * 272u + (uint32_t)k * 2u;
        *(__nv_bfloat16*)(smc + BHI_BYTE + off) = hi;
        *(__nv_bfloat16*)(smc + BLO_BYTE + off) = lo;
    }
    if (tid < 128) {
        // W1T row n=tid: k0..9 = hi(dW1[j][n]), k10..19 = lo, k20..29 = hi, rest 0
        __nv_bfloat16* r = (__nv_bfloat16*)(smc + W1T_BYTE + tid * 80);
        #pragma unroll
        for (int k = 0; k < 40; ++k) r[k] = __float2bfloat16(0.0f);
        #pragma unroll
        for (int j = 0; j < 10; ++j) {
            float w = dW1[j * 128 + tid];
            __nv_bfloat16 hi = __float2bfloat16(w);
            __nv_bfloat16 lo = __float2bfloat16(w - __bfloat162float(hi));
            r[j] = hi; r[10 + j] = lo; r[20 + j] = hi;
        }
        ((float*)(smc + WT_BYTE))[tid]  = dW1[106 * 128 + tid];
        ((float*)(smc + DB2_BYTE))[tid] = db2[tid];
        float* w3r = (float*)(smc + W3P_BYTE + tid * 48);
        #pragma unroll
        for (int j = 0; j < 10; ++j) w3r[j] = dW3[tid * 10 + j];
        w3r[10] = 0.0f; w3r[11] = 0.0f;
    }
    if (tid < 32) {
        float* g1r = (float*)(smc + GW1_BYTE + tid * 48);
        #pragma unroll
        for (int j = 0; j < 10; ++j) g1r[j] = gW1[j * 32 + tid];
        g1r[10] = gW1[10 * 32 + tid];
        g1r[11] = 0.0f;
        float* g2r = (float*)(smc + GW2_BYTE + tid * 48);
        #pragma unroll
        for (int j = 0; j < 10; ++j) g2r[j] = gW2[tid * 10 + j];
        g2r[10] = 0.0f; g2r[11] = 0.0f;
        ((float*)(smc + GB1_BYTE))[tid] = gb1[tid];
    }
    if (tid < 16) {
        ((float*)(smc + GB2_BYTE))[tid] = (tid < 10) ? gb2[tid] : 0.0f;
        ((float*)(smc + DB3_BYTE))[tid] = (tid < 10) ? db3[tid] : 0.0f;
    }
    for (int i = tid; i <= nstep && i < 128; i += TPB)
        ((float*)(smc + TS_BYTE))[i] = ts[i];

    // ---- context encoders -> C[128] -> g_C [col4][elem] ----
    if (elem < Bn) {
        float actv[6], rsv[3];
        #pragma unroll
        for (int j = 0; j < 6; ++j) actv[j] = activity[elem * 6 + j];
        #pragma unroll
        for (int j = 0; j < 3; ++j) rsv[j] = rest[elem * 3 + j];
        float ha[32];
        #pragma unroll
        for (int o = 0; o < 32; ++o) {
            float q = __ldg(&ab1[o]);
            #pragma unroll
            for (int j = 0; j < 6; ++j) q += actv[j] * __ldg(&aW1[j * 32 + o]);
            ha[o] = fmaxf(q, 0.0f);
        }
        float av[64];
        #pragma unroll
        for (int o = 0; o < 64; ++o) {
            float q = __ldg(&ab2[o]);
            #pragma unroll
            for (int j = 0; j < 32; ++j) q += ha[j] * __ldg(&aW2[j * 64 + o]);
            av[o] = q;
        }
        float hr[16];
        #pragma unroll
        for (int o = 0; o < 16; ++o) {
            float q = __ldg(&rb1[o]);
            #pragma unroll
            for (int j = 0; j < 3; ++j) q += rsv[j] * __ldg(&rW1[j * 16 + o]);
            hr[o] = fmaxf(q, 0.0f);
        }
        float rv[32];
        #pragma unroll
        for (int o = 0; o < 32; ++o) {
            float q = __ldg(&rb2[o]);
            #pragma unroll
            for (int j = 0; j < 16; ++j) q += hr[j] * __ldg(&rW2[j * 32 + o]);
            rv[o] = q;
        }
        for (int o4 = 0; o4 < 32; ++o4) {
            float cv[4];
            #pragma unroll
            for (int c = 0; c < 4; ++c) {
                int o = o4 * 4 + c;
                float q = __ldg(&db1[o]);
                #pragma unroll
                for (int j = 0; j < 64; ++j) q += av[j] * __ldg(&dW1[(10 + j) * 128 + o]);
                #pragma unroll
                for (int j = 0; j < 32; ++j) q += rv[j] * __ldg(&dW1[(74 + j) * 128 + o]);
                cv[c] = q;
            }
            g_C[(size_t)o4 * Bn + elem] = make_float4(cv[0], cv[1], cv[2], cv[3]);
        }
    }
    __syncthreads();   // g_C visible CTA-wide; smem staged

    float z[10];
    if (active) {
        // ---- repack C into fragment layout g_Cf ----
        #pragma unroll
        for (int mt = 0; mt < 2; ++mt)
            for (int nt = 0; nt < 16; ++nt) {
                int R0 = elemBase + mt * 16 + gid;
                int o4 = 2 * nt + (tid4 >> 1);
                float4 v0 = g_C[(size_t)o4 * Bn + R0];
                float4 v1 = g_C[(size_t)o4 * Bn + R0 + 8];
                float4 fr;
                if (tid4 & 1) { fr.x = v0.z; fr.y = v0.w; fr.z = v1.z; fr.w = v1.w; }
                else          { fr.x = v0.x; fr.y = v0.y; fr.z = v1.x; fr.w = v1.y; }
                g_Cf[((size_t)gw * 32 + mt * 16 + nt) * 32 + lane] = fr;
            }
        // z0 + output row 0
        #pragma unroll
        for (int j = 0; j < 10; ++j) z[j] = z0[elem * 10 + j];
        float2* op0 = (float2*)(out + (size_t)elem * 10);
        #pragma unroll
        for (int j = 0; j < 5; ++j) op0[j] = make_float2(z[2 * j], z[2 * j + 1]);
    }
    if (!active) return;    // no further __syncthreads

    // precomputed addresses
    const uint32_t zwarp = sbase + ZBUF_BYTE + (uint32_t)wid * (32 * 80);
    const uint32_t zaL   = zwarp + (uint32_t)(lane & 15) * 80u + ((uint32_t)(lane >> 4) & 1u) * 16u;
    const uint32_t w1L   = sbase + W1T_BYTE + (uint32_t)(lane & 7) * 80u
                         + (((uint32_t)lane >> 3) & 1u) * 16u + (((uint32_t)lane >> 4) & 1u) * 640u;
    const uint32_t bLdmLane = (uint32_t)(lane & 7) * 272u + ((uint32_t)lane >> 3) * 16u;
    float* route = (float*)(smc + ROUTE_BYTE + wid * 32 * 48);
    const float* tsf = (const float*)(smc + TS_BYTE);
    const float4* cfp = &g_Cf[(size_t)gw * 32 * 32 + lane];

    // ================= SDE integration (warp-synchronous) =================
    for (int s = 0; s < nstep; ++s) {
        const float t  = tsf[s];
        const float dt = tsf[s + 1] - t;
        const float sq = sqrtf(dt);

        // ---- z-aug row: [z_hi | z_hi | z_lo | 0] as 16 bf16x2 ----
        {
            unsigned short hs[10]; float zl[10];
            #pragma unroll
            for (int j = 0; j < 10; ++j) {
                __nv_bfloat16 h = __float2bfloat16(z[j]);
                hs[j] = __bfloat16_as_ushort(h);
                zl[j] = z[j] - __bfloat162float(h);
            }
            uint32_t p[16];
            #pragma unroll
            for (int i = 0; i < 5; ++i) {
                p[i] = (uint32_t)hs[2 * i] | ((uint32_t)hs[2 * i + 1] << 16);
                p[5 + i] = p[i];
                p[10 + i] = bf16x2_of(zl[2 * i], zl[2 * i + 1]);
            }
            p[15] = 0u;
            uint32_t dst = zwarp + (uint32_t)lane * 80u;
            asm volatile("st.shared.v4.b32 [%0], {%1,%2,%3,%4};" :: "r"(dst),
                "r"(p[0]), "r"(p[1]), "r"(p[2]), "r"(p[3]));
            asm volatile("st.shared.v4.b32 [%0], {%1,%2,%3,%4};" :: "r"(dst + 16),
                "r"(p[4]), "r"(p[5]), "r"(p[6]), "r"(p[7]));
            asm volatile("st.shared.v4.b32 [%0], {%1,%2,%3,%4};" :: "r"(dst + 32),
                "r"(p[8]), "r"(p[9]), "r"(p[10]), "r"(p[11]));
            asm volatile("st.shared.v4.b32 [%0], {%1,%2,%3,%4};" :: "r"(dst + 48),
                "r"(p[12]), "r"(p[13]), "r"(p[14]), "r"(p[15]));
        }
        __syncwarp();

        uint32_t za[2][2][4];
        #pragma unroll
        for (int mt = 0; mt < 2; ++mt)
            #pragma unroll
            for (int ks = 0; ks < 2; ++ks)
                ldm_x4(za[mt][ks], zaL + (uint32_t)mt * 1280u + (uint32_t)ks * 32u);

        // ---- GEMM1: h1 = tanh(zaug @ W1T + C + t*wt) -> A-frags in registers ----
        uint32_t af[2][8][4];
        #pragma unroll
        for (int mt = 0; mt < 2; ++mt) {
            float a1[16][4];
            #pragma unroll
            for (int nt = 0; nt < 16; ++nt) {
                float4 cf = __ldg(cfp + (mt * 16 + nt) * 32);
                float2 w2 = *(const float2*)(smc + WT_BYTE + (nt * 8 + qc) * 4);
                a1[nt][0] = fmaf(t, w2.x, cf.x);
                a1[nt][1] = fmaf(t, w2.y, cf.y);
                a1[nt][2] = fmaf(t, w2.x, cf.z);
                a1[nt][3] = fmaf(t, w2.y, cf.w);
            }
            #pragma unroll
            for (int ks = 0; ks < 2; ++ks)
                #pragma unroll
                for (int i = 0; i < 8; ++i) {
                    uint32_t bw[4];
                    ldm_x4(bw, w1L + (uint32_t)i * 1280u + (uint32_t)ks * 32u);
                    mma16816(a1[2 * i],     za[mt][ks], bw[0], bw[1]);
                    mma16816(a1[2 * i + 1], za[mt][ks], bw[2], bw[3]);
                }
            #pragma unroll
            for (int kt = 0; kt < 8; ++kt) {
                af[mt][kt][0] = bf16x2_of(tanh_hw(a1[2 * kt][0]),     tanh_hw(a1[2 * kt][1]));
                af[mt][kt][1] = bf16x2_of(tanh_hw(a1[2 * kt][2]),     tanh_hw(a1[2 * kt][3]));
                af[mt][kt][2] = bf16x2_of(tanh_hw(a1[2 * kt + 1][0]), tanh_hw(a1[2 * kt + 1][1]));
                af[mt][kt][3] = bf16x2_of(tanh_hw(a1[2 * kt + 1][2]), tanh_hw(a1[2 * kt + 1][3]));
            }
        }

        // ---- GEMM2 (hi+lo) + scalar epilogue ----
        ull dzp[4][5];
        #pragma unroll
        for (int ss = 0; ss < 4; ++ss)
            #pragma unroll
            for (int jj = 0; jj < 5; ++jj) dzp[ss][jj] = pack2(0.0f, 0.0f);

        #pragma unroll
        for (int ng = 0; ng < 4; ++ng) {
            float acc[2][4][4];
            #pragma unroll
            for (int ni = 0; ni < 4; ++ni) {
                float2 d2 = *(const float2*)(smc + DB2_BYTE + ((ng * 4 + ni) * 8 + qc) * 4);
                #pragma unroll
                for (int mt = 0; mt < 2; ++mt) {
                    acc[mt][ni][0] = d2.x; acc[mt][ni][1] = d2.y;
                    acc[mt][ni][2] = d2.x; acc[mt][ni][3] = d2.y;
                }
            }
            #pragma unroll
            for (int pass = 0; pass < 2; ++pass) {
                const uint32_t bb = sbase + (pass ? BLO_BYTE : BHI_BYTE) + bLdmLane;
                #pragma unroll
                for (int ni = 0; ni < 4; ++ni) {
                    const uint32_t brow = bb + (uint32_t)((ng * 4 + ni) * 8) * 272u;
                    #pragma unroll
                    for (int ktp = 0; ktp < 4; ++ktp) {
                        uint32_t r[4];
                        ldm_x4(r, brow + (uint32_t)ktp * 64u);
                        mma16816(acc[0][ni], af[0][2 * ktp],     r[0], r[1]);
                        mma16816(acc[1][ni], af[1][2 * ktp],     r[0], r[1]);
                        mma16816(acc[0][ni], af[0][2 * ktp + 1], r[2], r[3]);
                        mma16816(acc[1][ni], af[1][2 * ktp + 1], r[2], r[3]);
                    }
                }
            }
            #pragma unroll
            for (int ni = 0; ni < 4; ++ni) {
                const int cb = (ng * 4 + ni) * 8 + qc;
                const ull* w3a = (const ull*)(smc + W3P_BYTE + cb * 48);
                const ull* w3b = (const ull*)(smc + W3P_BYTE + (cb + 1) * 48);
                ull wa[5], wb[5];
                #pragma unroll
                for (int jj = 0; jj < 5; ++jj) { wa[jj] = w3a[jj]; wb[jj] = w3b[jj]; }
                #pragma unroll
                for (int mt = 0; mt < 2; ++mt) {
                    float h0 = tanh_hw(acc[mt][ni][0]);
                    float h1 = tanh_hw(acc[mt][ni][1]);
                    float h2 = tanh_hw(acc[mt][ni][2]);
                    float h3 = tanh_hw(acc[mt][ni][3]);
                    ull p0 = pack2(h0, h0), p1 = pack2(h1, h1);
                    ull p2 = pack2(h2, h2), p3 = pack2(h3, h3);
                    #pragma unroll
                    for (int jj = 0; jj < 5; ++jj) {
                        dzp[mt * 2][jj]     = ffma2(p0, wa[jj], dzp[mt * 2][jj]);
                        dzp[mt * 2][jj]     = ffma2(p1, wb[jj], dzp[mt * 2][jj]);
                        dzp[mt * 2 + 1][jj] = ffma2(p2, wa[jj], dzp[mt * 2 + 1][jj]);
                        dzp[mt * 2 + 1][jj] = ffma2(p3, wb[jj], dzp[mt * 2 + 1][jj]);
                    }
                }
            }
        }

        // ---- quad reduce + route dz to owner lane ----
        float dzf[4][10];
        #pragma unroll
        for (int ss = 0; ss < 4; ++ss)
            #pragma unroll
            for (int jj = 0; jj < 5; ++jj)
                unpack2(dzp[ss][jj], dzf[ss][2 * jj], dzf[ss][2 * jj + 1]);
        #pragma unroll
        for (int ss = 0; ss < 4; ++ss)
            #pragma unroll
            for (int j = 0; j < 10; ++j) {
                float v = dzf[ss][j];
                v += __shfl_xor_sync(0xffffffffu, v, 1);
                v += __shfl_xor_sync(0xffffffffu, v, 2);
                dzf[ss][j] = v;
            }
        if (tid4 == 0) {
            #pragma unroll
            for (int ss = 0; ss < 4; ++ss) {
                const int row = ((ss >> 1) << 4) + ((ss & 1) << 3) + gid;
                float2* rp = (float2*)(route + row * 12);
                #pragma unroll
                for (int jj = 0; jj < 5; ++jj)
                    rp[jj] = make_float2(dzf[ss][2 * jj], dzf[ss][2 * jj + 1]);
            }
        }
        __syncwarp();
        float dz[10];
        {
            const float* rp = route + lane * 12;
            const float* d3 = (const float*)(smc + DB3_BYTE);
            #pragma unroll
            for (int j = 0; j < 10; ++j) dz[j] = rp[j] + d3[j];
        }
        __syncwarp();

        // ---- diffusion MLP 11 -> 32 -> 10 ----
        ull zp[5];
        #pragma unroll
        for (int j = 0; j < 5; ++j) zp[j] = pack2(z[2 * j], z[2 * j + 1]);
        ull gvp[5];
        {
            const float2* g2 = (const float2*)(smc + GB2_BYTE);
            #pragma unroll
            for (int jj = 0; jj < 5; ++jj) gvp[jj] = pack2(g2[jj].x, g2[jj].y);
        }
        const float* gb1f = (const float*)(smc + GB1_BYTE);
        #pragma unroll 4
        for (int o = 0; o < 32; ++o) {
            const float4* g1 = (const float4*)(smc + GW1_BYTE + o * 48);
            float4 w0 = g1[0], w4 = g1[1], w8 = g1[2];
            ull p2 = pack2(gb1f[o], t * w8.z);
            p2 = ffma2(zp[0], pack2(w0.x, w0.y), p2);
            p2 = ffma2(zp[1], pack2(w0.z, w0.w), p2);
            p2 = ffma2(zp[2], pack2(w4.x, w4.y), p2);
            p2 = ffma2(zp[3], pack2(w4.z, w4.w), p2);
            p2 = ffma2(zp[4], pack2(w8.x, w8.y), p2);
            float plo, phi; unpack2(p2, plo, phi);
            float q = softplus_(plo + phi);
            ull qq = pack2(q, q);
            const ull* g2w = (const ull*)(smc + GW2_BYTE + o * 48);
            #pragma unroll
            for (int jj = 0; jj < 5; ++jj) gvp[jj] = ffma2(qq, g2w[jj], gvp[jj]);
        }

        // ---- Euler-Maruyama update + stream out ----
        const float2* np = (const float2*)(noise + ((size_t)s * Bn + elem) * 10);
        float2*       op = (float2*)(out + ((size_t)(s + 1) * Bn + elem) * 10);
        #pragma unroll
        for (int j = 0; j < 5; ++j) {
            float glo, ghi; unpack2(gvp[j], glo, ghi);
            float2 e = np[j];
            z[2 * j]     += dz[2 * j]     * dt + glo * sq * e.x;
            z[2 * j + 1] += dz[2 * j + 1] * dt + ghi * sq * e.y;
            op[j] = make_float2(z[2 * j], z[2 * j + 1]);
        }
    }
}

extern "C" void kernel_launch(void* const* d_in, const int* in_sizes, int n_in,
                              void* d_out, int out_size) {
    const float* z0       = (const float*)d_in[0];
    const float* activity = (const float*)d_in[1];
    const float* rest     = (const float*)d_in[2];
    const float* ts       = (const float*)d_in[3];
    const float* noise    = (const float*)d_in[4];
    const float* aW1 = (const float*)d_in[5];
    const float* ab1 = (const float*)d_in[6];
    const float* aW2 = (const float*)d_in[7];
    const float* ab2 = (const float*)d_in[8];
    const float* rW1 = (const float*)d_in[9];
    const float* rb1 = (const float*)d_in[10];
    const float* rW2 = (const float*)d_in[11];
    const float* rb2 = (const float*)d_in[12];
    const float* dW1 = (const float*)d_in[13];
    const float* db1 = (const float*)d_in[14];
    const float* dW2 = (const float*)d_in[15];
    const float* db2 = (const float*)d_in[16];
    const float* dW3 = (const float*)d_in[17];
    const float* db3 = (const float*)d_in[18];
    const float* gW1 = (const float*)d_in[19];
    const float* gb1 = (const float*)d_in[20];
    const float* gW2 = (const float*)d_in[21];
    const float* gb2 = (const float*)d_in[22];

    int B     = in_sizes[0] / 10;
    int nstep = in_sizes[3] - 1;

    cudaFuncSetAttribute(sde_hmma, cudaFuncAttributeMaxDynamicSharedMemorySize,
                         SMEM_BYTES);
    int grid = (B + TPB - 1) / TPB;
    sde_hmma<<<grid, TPB, SMEM_BYTES>>>(
        z0, activity, rest, ts, noise,
        aW1, ab1, aW2, ab2, rW1, rb1, rW2, rb2,
        dW1, db1, dW2, db2, dW3, db3,
        gW1, gb1, gW2, gb2,
        (float*)d_out, B, nstep);
}